// round 14
// baseline (speedup 1.0000x reference)
#include <cuda_runtime.h>
#include <cuda_bf16.h>
#include <math.h>
#include <stdint.h>

// Problem constants
#define BB   4
#define LL   2048
#define NH   8
#define DH   64
#define DIN  512
#define DMID 2048
#define MROWS (BB*LL)    // 8192

// ---------------- scratch (__device__ globals; no allocation allowed) -------
__device__ float g_V  [MROWS * DIN];
__device__ float g_tmp[MROWS * DIN];
__device__ float g_xa [MROWS * DIN];

// split-bf16 buffers
__device__ __nv_bfloat16 g_ahi[MROWS * DMID];
__device__ __nv_bfloat16 g_alo[MROWS * DMID];
__device__ __nv_bfloat16 g_qh[MROWS * DIN], g_ql[MROWS * DIN];
__device__ __nv_bfloat16 g_kh[MROWS * DIN], g_kl[MROWS * DIN];
__device__ __nv_bfloat16 g_ath[MROWS * DIN], g_atl[MROWS * DIN];
__device__ __nv_bfloat16 g_vth[BB * NH * DH * LL];   // [bh][dim][key] hi
__device__ __nv_bfloat16 g_vtl[BB * NH * DH * LL];   // [bh][dim][key] lo
// transposed split-bf16 weights  [N, K]
__device__ __nv_bfloat16 g_wqh[DIN*DIN],  g_wql[DIN*DIN];
__device__ __nv_bfloat16 g_wkh[DIN*DIN],  g_wkl[DIN*DIN];
__device__ __nv_bfloat16 g_wvh[DIN*DIN],  g_wvl[DIN*DIN];
__device__ __nv_bfloat16 g_woh[DIN*DIN],  g_wol[DIN*DIN];
__device__ __nv_bfloat16 g_w1h[DMID*DIN], g_w1l[DMID*DIN];
__device__ __nv_bfloat16 g_w2h[DIN*DMID], g_w2l[DIN*DMID];

// ---------------- PTX helpers (compute_103-safe) ----------------------------
__device__ __forceinline__ uint32_t smem_u32(const void* p) {
    uint32_t a;
    asm("{ .reg .u64 t; cvta.to.shared.u64 t, %1; cvt.u32.u64 %0, t; }"
        : "=r"(a) : "l"(p));
    return a;
}
__device__ __forceinline__ void ldsm_x4(uint32_t* r, uint32_t addr) {
    asm volatile("ldmatrix.sync.aligned.m8n8.x4.shared.b16 {%0,%1,%2,%3}, [%4];"
        : "=r"(r[0]), "=r"(r[1]), "=r"(r[2]), "=r"(r[3]) : "r"(addr));
}
__device__ __forceinline__ void mma16816(float* d, const uint32_t* a,
                                         const uint32_t* b) {
    asm volatile("mma.sync.aligned.m16n8k16.row.col.f32.bf16.bf16.f32 "
        "{%0,%1,%2,%3}, {%4,%5,%6,%7}, {%8,%9}, {%0,%1,%2,%3};"
        : "+f"(d[0]), "+f"(d[1]), "+f"(d[2]), "+f"(d[3])
        : "r"(a[0]), "r"(a[1]), "r"(a[2]), "r"(a[3]), "r"(b[0]), "r"(b[1]));
}
#define CP_ASYNC16(dst, src) \
    asm volatile("cp.async.cg.shared.global [%0], [%1], 16;" :: "r"(dst), "l"(src))
#define CP_COMMIT() asm volatile("cp.async.commit_group;" ::: "memory")
#define CP_WAIT1()  asm volatile("cp.async.wait_group 1;" ::: "memory")
#define CP_WAIT0()  asm volatile("cp.async.wait_group 0;" ::: "memory")

__device__ __forceinline__ uint32_t pack2bf(float x0, float x1) {
    __nv_bfloat16 h0 = __float2bfloat16(x0);
    __nv_bfloat16 h1 = __float2bfloat16(x1);
    return ((uint32_t)__bfloat16_as_ushort(h1) << 16) | __bfloat16_as_ushort(h0);
}
__device__ __forceinline__ void split2(float x0, float x1,
                                       uint32_t& hi, uint32_t& lo) {
    __nv_bfloat16 h0 = __float2bfloat16(x0);
    __nv_bfloat16 h1 = __float2bfloat16(x1);
    hi = ((uint32_t)__bfloat16_as_ushort(h1) << 16) | __bfloat16_as_ushort(h0);
    lo = pack2bf(x0 - __bfloat162float(h0), x1 - __bfloat162float(h1));
}

// ---------------- split-bf16 HMMA GEMM (R5-validated mainloop) ---------------
#define KCH   32
#define RSTRB 80
#define OPB   (128 * RSTRB)
#define STAGEB (4 * OPB)
__global__ __launch_bounds__(256, 2) void hgemm3_kernel(
    const __nv_bfloat16* __restrict__ Ahi, const __nv_bfloat16* __restrict__ Alo,
    const __nv_bfloat16* __restrict__ Bh,  const __nv_bfloat16* __restrict__ Bl,
    float* __restrict__ C,
    __nv_bfloat16* __restrict__ Chi, __nv_bfloat16* __restrict__ Clo,
    int K, int N, int do_relu, int mode)
{
    extern __shared__ char smem[];
    const uint32_t sb = smem_u32(smem);
    const int tid  = threadIdx.x;
    const int wid  = tid >> 5;
    const int lane = tid & 31;
    const int wm   = wid >> 2;
    const int wn   = wid & 3;
    const int bx = blockIdx.x, by = blockIdx.y;

    const size_t aBase = (size_t)by * 128 * K;
    const size_t bBase = (size_t)bx * 128 * K;
    const __nv_bfloat16* tp[4] = { Ahi + aBase, Alo + aBase, Bh + bBase, Bl + bBase };

    const int nk = K / KCH;

    float acc[4][4][4];
    #pragma unroll
    for (int i = 0; i < 4; i++)
        #pragma unroll
        for (int j = 0; j < 4; j++)
            #pragma unroll
            for (int v = 0; v < 4; v++) acc[i][j][v] = 0.f;

    auto load_stage = [&](int kt, int stage) {
        const size_t koff = (size_t)kt * KCH;
        const uint32_t sbase = sb + stage * STAGEB;
        #pragma unroll
        for (int i = 0; i < 8; i++) {
            int idx = tid + i * 256;
            int op  = idx >> 9;
            int rem = idx & 511;
            int r   = rem >> 2;
            int s   = rem & 3;
            const __nv_bfloat16* src = tp[op] + (size_t)r * K + koff + s * 8;
            uint32_t dst = sbase + op * OPB + r * RSTRB + s * 16;
            CP_ASYNC16(dst, src);
        }
        CP_COMMIT();
    };

    load_stage(0, 0);

    const int a_m  = (lane & 15);
    const int a_kb = (lane >> 4) * 16;
    const int b_n  = (lane & 7) + ((lane >> 4) << 3);
    const int b_kb = ((lane >> 3) & 1) * 16;

    for (int kt = 0; kt < nk; kt++) {
        if (kt + 1 < nk) { load_stage(kt + 1, (kt + 1) & 1); CP_WAIT1(); }
        else             { CP_WAIT0(); }
        __syncthreads();

        const uint32_t st = sb + (kt & 1) * STAGEB;
        #pragma unroll
        for (int ks = 0; ks < 2; ks++) {
            const uint32_t kofs = ks * 32;

            uint32_t bh[2][4], bl[2][4];
            #pragma unroll
            for (int np = 0; np < 2; np++) {
                int n = wn * 32 + np * 16 + b_n;
                ldsm_x4(bh[np], st + 2 * OPB + n * RSTRB + kofs + b_kb);
                ldsm_x4(bl[np], st + 3 * OPB + n * RSTRB + kofs + b_kb);
            }

            uint32_t af[4][4];
            #pragma unroll
            for (int mt = 0; mt < 4; mt++) {
                int m = wm * 64 + mt * 16 + a_m;
                ldsm_x4(af[mt], st + 0 * OPB + m * RSTRB + kofs + a_kb);
            }
            #pragma unroll
            for (int mt = 0; mt < 4; mt++)
                #pragma unroll
                for (int nt = 0; nt < 4; nt++) {
                    mma16816(acc[mt][nt], af[mt], &bh[nt >> 1][(nt & 1) * 2]);
                    mma16816(acc[mt][nt], af[mt], &bl[nt >> 1][(nt & 1) * 2]);
                }
            #pragma unroll
            for (int mt = 0; mt < 4; mt++) {
                int m = wm * 64 + mt * 16 + a_m;
                ldsm_x4(af[mt], st + 1 * OPB + m * RSTRB + kofs + a_kb);
            }
            #pragma unroll
            for (int mt = 0; mt < 4; mt++)
                #pragma unroll
                for (int nt = 0; nt < 4; nt++)
                    mma16816(acc[mt][nt], af[mt], &bh[nt >> 1][(nt & 1) * 2]);
        }
        __syncthreads();
    }

    const int rbase = by * 128 + wm * 64 + (lane >> 2);
    const int cbase = bx * 128 + wn * 32 + (lane & 3) * 2;
    #pragma unroll
    for (int mt = 0; mt < 4; mt++)
        #pragma unroll
        for (int nt = 0; nt < 4; nt++) {
            float* d = acc[mt][nt];
            if (do_relu) {
                d[0] = fmaxf(d[0], 0.f); d[1] = fmaxf(d[1], 0.f);
                d[2] = fmaxf(d[2], 0.f); d[3] = fmaxf(d[3], 0.f);
            }
            int r = rbase + mt * 16;
            int c = cbase + nt * 8;
            if (mode == 0) {
                *(float2*)(C + (size_t)r * N + c)       = make_float2(d[0], d[1]);
                *(float2*)(C + (size_t)(r + 8) * N + c) = make_float2(d[2], d[3]);
            } else {
                uint32_t h0, l0, h1, l1;
                split2(d[0], d[1], h0, l0);
                split2(d[2], d[3], h1, l1);
                *(uint32_t*)(Chi + (size_t)r * N + c)       = h0;
                *(uint32_t*)(Clo + (size_t)r * N + c)       = l0;
                *(uint32_t*)(Chi + (size_t)(r + 8) * N + c) = h1;
                *(uint32_t*)(Clo + (size_t)(r + 8) * N + c) = l1;
            }
        }
}

// ---------------- fp32 -> (hi, lo) bf16 split --------------------------------
__global__ __launch_bounds__(256) void cvt_split_kernel(
    const float* __restrict__ x, __nv_bfloat16* __restrict__ hi,
    __nv_bfloat16* __restrict__ lo, int n4)
{
    int i = blockIdx.x * 256 + threadIdx.x;
    if (i >= n4) return;
    float4 v = ((const float4*)x)[i];
    uint32_t h0, l0, h1, l1;
    split2(v.x, v.y, h0, l0);
    split2(v.z, v.w, h1, l1);
    uint32_t* hp = (uint32_t*)hi;
    uint32_t* lp = (uint32_t*)lo;
    hp[2*i]   = h0;
    hp[2*i+1] = h1;
    lp[2*i]   = l0;
    lp[2*i+1] = l1;
}

// ---------------- weight transpose + split -----------------------------------
__global__ __launch_bounds__(256) void wtrans_kernel(
    const float* __restrict__ W, __nv_bfloat16* __restrict__ Thi,
    __nv_bfloat16* __restrict__ Tlo, int K, int N)
{
    __shared__ float t[32][33];
    const int tx = threadIdx.x, ty = threadIdx.y;
    const int n0 = blockIdx.x * 32, k0 = blockIdx.y * 32;
    #pragma unroll
    for (int i = 0; i < 4; i++)
        t[ty + 8*i][tx] = W[(size_t)(k0 + ty + 8*i) * N + n0 + tx];
    __syncthreads();
    #pragma unroll
    for (int i = 0; i < 4; i++) {
        float v = t[tx][ty + 8*i];
        __nv_bfloat16 h = __float2bfloat16(v);
        __nv_bfloat16 l = __float2bfloat16(v - __bfloat162float(h));
        size_t o = (size_t)(n0 + ty + 8*i) * K + k0 + tx;
        Thi[o] = h;
        Tlo[o] = l;
    }
}

// ---------------- V transpose -> bf16 hi/lo [bh][dim][key] -------------------
__global__ __launch_bounds__(256) void vtrans_kernel(
    const float* __restrict__ V, __nv_bfloat16* __restrict__ Vth,
    __nv_bfloat16* __restrict__ Vtl)
{
    __shared__ float t[32][33];
    const int tx = threadIdx.x, ty = threadIdx.y;   // block (32, 8)
    const int l0 = blockIdx.x * 32;
    const int d0 = blockIdx.y * 32;
    const int bh = blockIdx.z;                      // b*NH + h
    const int b  = bh >> 3, h = bh & 7;
    #pragma unroll
    for (int i = 0; i < 4; i++)
        t[ty + 8*i][tx] = V[(size_t)(b * LL + l0 + ty + 8*i) * DIN + h * DH + d0 + tx];
    __syncthreads();
    #pragma unroll
    for (int i = 0; i < 4; i++) {
        float v = t[tx][ty + 8*i];                  // (l = l0+tx, d = d0+ty+8i)
        __nv_bfloat16 hh = __float2bfloat16(v);
        __nv_bfloat16 lo = __float2bfloat16(v - __bfloat162float(hh));
        size_t o = ((size_t)bh * DH + d0 + ty + 8*i) * LL + l0 + tx;
        Vth[o] = hh;
        Vtl[o] = lo;
    }
}

// ---------------- HMMA flash attention: 128-query tiles ----------------------
// grid (LL/128, NH, BB), 256 threads. Warp w: score rows w*16 (all 64 keys),
// PV rows w*16 (all 64 dims). K single-buf, V double-buf, mask aliased in Ss.
#define SRB  144                      // bf16 tile row stride (bytes)
#define FSTR 68                       // fp32 tile stride (floats)
#define S_QH 0                        // 128 rows: 18432
#define S_QL (S_QH + 128 * SRB)       // 18432
#define S_KH (S_QL + 128 * SRB)       // 36864 (64 rows: 9216)
#define S_KL (S_KH + 64 * SRB)        // 46080
#define S_V0 (S_KL + 64 * SRB)        // 55296 (2 bufs x (hi 9216 + lo 9216))
#define S_PH (S_V0 + 4 * 64 * SRB)    // 92160 (128 rows: 18432)
#define S_PL (S_PH + 128 * SRB)       // 110592
#define S_S  (S_PL + 128 * SRB)       // 129024 (fp32 128x68 = 34816; mask target)
#define S_AR (S_S + 128 * FSTR * 4)   // 163840 (alpha, 128 floats)
#define S_LR (S_AR + 512)             // 164352 (l_run, 128 floats)
#define ATT_SMEM (S_LR + 512)         // 164864 (1 CTA/SM)
__global__ __launch_bounds__(256) void attn_kernel(
    const __nv_bfloat16* __restrict__ Qh, const __nv_bfloat16* __restrict__ Ql,
    const __nv_bfloat16* __restrict__ Kh, const __nv_bfloat16* __restrict__ Kl,
    const __nv_bfloat16* __restrict__ Vth, const __nv_bfloat16* __restrict__ Vtl,
    const float* __restrict__ mask,
    __nv_bfloat16* __restrict__ Oh, __nv_bfloat16* __restrict__ Ol)
{
    extern __shared__ char smem[];
    const uint32_t sb = smem_u32(smem);
    float* Ss   = (float*)(smem + S_S);
    float* arow = (float*)(smem + S_AR);
    float* lrow = (float*)(smem + S_LR);

    const int qt = blockIdx.x;
    const int h  = blockIdx.y;
    const int b  = blockIdx.z;
    const int bh = b * NH + h;

    const int tid  = threadIdx.x;
    const int wid  = tid >> 5;
    const int lane = tid & 31;
    const int tx   = tid & 15;
    const int ty   = tid >> 4;
    const int r0   = ty * 4;
    const int c0   = tx * 4;

    const size_t krow0base = (size_t)b * LL;
    const size_t vrow0 = (size_t)bh * DH;
    const float* maskb = mask + ((size_t)b * LL + qt * 128) * LL;

    auto load_kv_mask = [&](int kt) {
        const size_t krow0 = krow0base + kt * 64;
        const uint32_t svb = sb + S_V0 + (kt & 1) * 18432;
        #pragma unroll
        for (int i = 0; i < 4; i++) {
            int idx = tid + i * 256;
            int op  = idx >> 9;
            int rem = idx & 511;
            int r   = rem >> 3;
            int seg = rem & 7;
            const __nv_bfloat16* src =
                (op ? Kl : Kh) + (krow0 + r) * DIN + h * DH + seg * 8;
            CP_ASYNC16(sb + (op ? S_KL : S_KH) + r * SRB + seg * 16, src);
        }
        #pragma unroll
        for (int i = 0; i < 4; i++) {
            int idx = tid + i * 256;
            int op  = idx >> 9;                    // 0: Vth, 1: Vtl
            int rem = idx & 511;
            int r   = rem >> 3;                    // dim 0..63
            int seg = rem & 7;
            const __nv_bfloat16* src =
                (op ? Vtl : Vth) + (vrow0 + r) * LL + kt * 64 + seg * 8;
            CP_ASYNC16(svb + op * 9216 + r * SRB + seg * 16, src);
        }
        // mask tile [128][64] fp32 into Ss (FSTR-padded rows)
        #pragma unroll
        for (int i = 0; i < 8; i++) {
            int idx = tid + i * 256;               // 0..2047
            int r   = idx >> 4;
            int s   = idx & 15;
            const float* src = maskb + (size_t)r * LL + kt * 64 + s * 4;
            CP_ASYNC16(sb + S_S + r * (FSTR * 4) + s * 16, src);
        }
        CP_COMMIT();
    };

    // ---- prologue: Q (128 rows) + tile 0 in one group ----
    {
        const size_t qrow0 = (size_t)(b * LL + qt * 128);
        #pragma unroll
        for (int i = 0; i < 8; i++) {
            int idx = tid + i * 256;          // 0..2047
            int op  = idx >> 10;              // 0: Qh, 1: Ql
            int rem = idx & 1023;
            int r   = rem >> 3;
            int seg = rem & 7;
            const __nv_bfloat16* src =
                (op ? Ql : Qh) + (qrow0 + r) * DIN + h * DH + seg * 8;
            CP_ASYNC16(sb + (op ? S_QL : S_QH) + r * SRB + seg * 16, src);
        }
        load_kv_mask(0);        // commits (Q included in same group)
        CP_WAIT0();
    }
    __syncthreads();

    // HMMA lane addressing (R5/R8-validated)
    const int a_m  = (lane & 15);
    const int a_kb = (lane >> 4) * 16;
    const int b_n  = (lane & 7) + ((lane >> 4) << 3);
    const int b_kb = ((lane >> 3) & 1) * 16;
    const int qr  = wid * 16;              // warp's 16 rows (scores and PV)
    const int rl0 = qr + (lane >> 2);

    // ---- hoist Q fragments ----
    uint32_t qfh[4][4], qfl[4][4];
    #pragma unroll
    for (int k4 = 0; k4 < 4; k4++) {
        uint32_t ro = (qr + a_m) * SRB + k4 * 32 + a_kb;
        ldsm_x4(qfh[k4], sb + S_QH + ro);
        ldsm_x4(qfl[k4], sb + S_QL + ro);
    }

    float m_run[8], l_run[8];
    #pragma unroll
    for (int i = 0; i < 8; i++) { m_run[i] = -1.0e30f; l_run[i] = 0.f; }

    float oacc[8][4];
    #pragma unroll
    for (int j = 0; j < 8; j++)
        #pragma unroll
        for (int v = 0; v < 4; v++) oacc[j][v] = 0.f;

    const int nkt = LL / 64;
    for (int kt = 0; kt < nkt; kt++) {
        // ---- HMMA scores: warp -> 16 q rows x 64 keys; in-place mask fuse ----
        {
            float sc[8][4];
            #pragma unroll
            for (int j = 0; j < 8; j++)
                #pragma unroll
                for (int v = 0; v < 4; v++) sc[j][v] = 0.f;

            #pragma unroll
            for (int k4 = 0; k4 < 4; k4++) {
                uint32_t bhf[4][4], blf[4][4];
                #pragma unroll
                for (int np = 0; np < 4; np++) {
                    uint32_t rk = (np * 16 + b_n) * SRB + k4 * 32 + b_kb;
                    ldsm_x4(bhf[np], sb + S_KH + rk);
                    ldsm_x4(blf[np], sb + S_KL + rk);
                }
                #pragma unroll
                for (int j = 0; j < 8; j++) {
                    mma16816(sc[j], qfh[k4], &bhf[j >> 1][(j & 1) * 2]);
                    mma16816(sc[j], qfh[k4], &blf[j >> 1][(j & 1) * 2]);
                    mma16816(sc[j], qfl[k4], &bhf[j >> 1][(j & 1) * 2]);
                }
            }

            const int sr0 = qr + (lane >> 2);
            #pragma unroll
            for (int j = 0; j < 8; j++) {
                int col = j * 8 + 2 * (lane & 3);
                float2 mk0 = *(const float2*)&Ss[sr0 * FSTR + col];       // mask
                float2 mk1 = *(const float2*)&Ss[(sr0 + 8) * FSTR + col];
                *(float2*)&Ss[sr0 * FSTR + col] =
                    make_float2(fmaf(sc[j][0], 0.125f, mk0.x),
                                fmaf(sc[j][1], 0.125f, mk0.y));
                *(float2*)&Ss[(sr0 + 8) * FSTR + col] =
                    make_float2(fmaf(sc[j][2], 0.125f, mk1.x),
                                fmaf(sc[j][3], 0.125f, mk1.y));
            }
        }
        __syncthreads();

        // ---- fp32 online softmax over two 64-row halves ----
        #pragma unroll
        for (int half = 0; half < 2; half++) {
            float s[4][4];
            const int rbase = half * 64 + r0;
            #pragma unroll
            for (int i = 0; i < 4; i++)
                #pragma unroll
                for (int j = 0; j < 4; j++)
                    s[i][j] = Ss[(rbase + i) * FSTR + c0 + j];

            #pragma unroll
            for (int i = 0; i < 4; i++) {
                const int mi = half * 4 + i;
                float ml = fmaxf(fmaxf(s[i][0], s[i][1]), fmaxf(s[i][2], s[i][3]));
                #pragma unroll
                for (int off = 1; off < 16; off <<= 1)
                    ml = fmaxf(ml, __shfl_xor_sync(0xffffffffu, ml, off));

                float mnew  = fmaxf(m_run[mi], ml);
                float alpha = __expf(m_run[mi] - mnew);
                m_run[mi] = mnew;

                float lsum = 0.f;
                #pragma unroll
                for (int j = 0; j < 4; j++) {
                    float p = __expf(s[i][j] - mnew);
                    s[i][j] = p;
                    lsum += p;
                }
                #pragma unroll
                for (int off = 1; off < 16; off <<= 1)
                    lsum += __shfl_xor_sync(0xffffffffu, lsum, off);
                l_run[mi] = l_run[mi] * alpha + lsum;

                if (tx == 0) arow[rbase + i] = alpha;

                uint32_t h0, l0p, h1, l1p;
                split2(s[i][0], s[i][1], h0, l0p);
                split2(s[i][2], s[i][3], h1, l1p);
                uint32_t off0 = (rbase + i) * SRB + c0 * 2;
                *(uint32_t*)(smem + S_PH + off0)     = h0;
                *(uint32_t*)(smem + S_PH + off0 + 4) = h1;
                *(uint32_t*)(smem + S_PL + off0)     = l0p;
                *(uint32_t*)(smem + S_PL + off0 + 4) = l1p;
            }
        }
        __syncthreads();
        // K free, Ss free, V[(kt+1)&1] free -> prefetch next tile over PV
        if (kt + 1 < nkt) load_kv_mask(kt + 1);

        // ---- PV HMMA: warp -> 16 q rows x 64 dims, V buf kt&1 ----
        {
            const uint32_t svb = sb + S_V0 + (kt & 1) * 18432;
            float a0 = arow[rl0];
            float a1 = arow[rl0 + 8];
            #pragma unroll
            for (int j = 0; j < 8; j++) {
                oacc[j][0] *= a0; oacc[j][1] *= a0;
                oacc[j][2] *= a1; oacc[j][3] *= a1;
            }

            #pragma unroll
            for (int k4 = 0; k4 < 4; k4++) {
                uint32_t aph[4], apl[4];
                uint32_t ro = (qr + a_m) * SRB + k4 * 32 + a_kb;
                ldsm_x4(aph, sb + S_PH + ro);
                ldsm_x4(apl, sb + S_PL + ro);
                uint32_t bvh[4][4], bvl[4][4];
                #pragma unroll
                for (int np = 0; np < 4; np++) {
                    uint32_t rk = (np * 16 + b_n) * SRB + k4 * 32 + b_kb;
                    ldsm_x4(bvh[np], svb + rk);
                    ldsm_x4(bvl[np], svb + 9216 + rk);
                }
                #pragma unroll
                for (int j = 0; j < 8; j++) {
                    mma16816(oacc[j], aph, &bvh[j >> 1][(j & 1) * 2]);
                    mma16816(oacc[j], aph, &bvl[j >> 1][(j & 1) * 2]);
                    mma16816(oacc[j], apl, &bvh[j >> 1][(j & 1) * 2]);
                }
            }
        }

        if (kt + 1 < nkt) CP_WAIT0();
        __syncthreads();
    }

    // ---- publish l_run, split-bf16 epilogue ----
    if (tx == 0) {
        #pragma unroll
        for (int i = 0; i < 4; i++) {
            lrow[r0 + i]      = l_run[i];
            lrow[64 + r0 + i] = l_run[4 + i];
        }
    }
    __syncthreads();

    const float inv0 = 1.f / lrow[rl0];
    const float inv1 = 1.f / lrow[rl0 + 8];
    const size_t o0 = ((size_t)(b * LL + qt * 128 + rl0)) * DIN + h * DH
                    + 2 * (lane & 3);
    const size_t o1 = o0 + 8 * DIN;
    #pragma unroll
    for (int j = 0; j < 8; j++) {
        uint32_t h0, l0p, h1, l1p;
        split2(oacc[j][0] * inv0, oacc[j][1] * inv0, h0, l0p);
        split2(oacc[j][2] * inv1, oacc[j][3] * inv1, h1, l1p);
        *(uint32_t*)(Oh + o0 + 8 * j) = h0;
        *(uint32_t*)(Ol + o0 + 8 * j) = l0p;
        *(uint32_t*)(Oh + o1 + 8 * j) = h1;
        *(uint32_t*)(Ol + o1 + 8 * j) = l1p;
    }
}

// ---------------- residual + LayerNorm (optional split output) ---------------
__global__ __launch_bounds__(128) void ln_residual_kernel(
    const float* __restrict__ x, const float* __restrict__ y,
    float* __restrict__ o,
    __nv_bfloat16* __restrict__ ohi, __nv_bfloat16* __restrict__ olo,
    int emit_split)
{
    const int row = blockIdx.x;
    const int t   = threadIdx.x;
    const float* xr = x + (size_t)row * DIN;
    const float* yr = y + (size_t)row * DIN;

    float v[4];
    float s = 0.f, s2 = 0.f;
    #pragma unroll
    for (int i = 0; i < 4; i++) {
        float a = xr[t + 128 * i] + yr[t + 128 * i];
        v[i] = a;
        s  += a;
        s2 += a * a;
    }
    #pragma unroll
    for (int off = 16; off; off >>= 1) {
        s  += __shfl_xor_sync(0xffffffffu, s,  off);
        s2 += __shfl_xor_sync(0xffffffffu, s2, off);
    }
    __shared__ float ss[4], ss2[4];
    if ((t & 31) == 0) { ss[t >> 5] = s; ss2[t >> 5] = s2; }
    __syncthreads();
    s  = ss[0]  + ss[1]  + ss[2]  + ss[3];
    s2 = ss2[0] + ss2[1] + ss2[2] + ss2[3];

    const float mean = s * (1.f / DIN);
    const float var  = s2 * (1.f / DIN) - mean * mean;
    const float r    = rsqrtf(var + 1e-5f);

    float* orow = o + (size_t)row * DIN;
    #pragma unroll
    for (int i = 0; i < 4; i++) {
        float val = (v[i] - mean) * r;
        orow[t + 128 * i] = val;
        if (emit_split) {
            __nv_bfloat16 hh = __float2bfloat16(val);
            ohi[(size_t)row * DIN + t + 128 * i] = hh;
            olo[(size_t)row * DIN + t + 128 * i] =
                __float2bfloat16(val - __bfloat162float(hh));
        }
    }
}

// ---------------- launch -----------------------------------------------------
extern "C" void kernel_launch(void* const* d_in, const int* in_sizes, int n_in,
                              void* d_out, int out_size)
{
    const float* query = (const float*)d_in[0];
    const float* key   = (const float*)d_in[1];
    const float* value = (const float*)d_in[2];
    const float* mask  = (const float*)d_in[3];
    const float* WQ    = (const float*)d_in[4];
    const float* WK    = (const float*)d_in[5];
    const float* WV    = (const float*)d_in[6];
    const float* WO    = (const float*)d_in[7];
    const float* W1    = (const float*)d_in[8];
    const float* W2    = (const float*)d_in[9];
    float* out = (float*)d_out;

    float *Vp, *tmp, *xa;
    cudaGetSymbolAddress((void**)&Vp,  g_V);
    cudaGetSymbolAddress((void**)&tmp, g_tmp);
    cudaGetSymbolAddress((void**)&xa,  g_xa);

    __nv_bfloat16 *ahi, *alo, *qh, *ql, *kh, *kl, *ath, *atl, *vth, *vtl;
    __nv_bfloat16 *wqh, *wql, *wkh, *wkl, *wvh, *wvl;
    __nv_bfloat16 *woh, *wol, *w1h, *w1l, *w2h, *w2l;
    cudaGetSymbolAddress((void**)&ahi, g_ahi);
    cudaGetSymbolAddress((void**)&alo, g_alo);
    cudaGetSymbolAddress((void**)&qh,  g_qh);
    cudaGetSymbolAddress((void**)&ql,  g_ql);
    cudaGetSymbolAddress((void**)&kh,  g_kh);
    cudaGetSymbolAddress((void**)&kl,  g_kl);
    cudaGetSymbolAddress((void**)&ath, g_ath);
    cudaGetSymbolAddress((void**)&atl, g_atl);
    cudaGetSymbolAddress((void**)&vth, g_vth);
    cudaGetSymbolAddress((void**)&vtl, g_vtl);
    cudaGetSymbolAddress((void**)&wqh, g_wqh);
    cudaGetSymbolAddress((void**)&wql, g_wql);
    cudaGetSymbolAddress((void**)&wkh, g_wkh);
    cudaGetSymbolAddress((void**)&wkl, g_wkl);
    cudaGetSymbolAddress((void**)&wvh, g_wvh);
    cudaGetSymbolAddress((void**)&wvl, g_wvl);
    cudaGetSymbolAddress((void**)&woh, g_woh);
    cudaGetSymbolAddress((void**)&wol, g_wol);
    cudaGetSymbolAddress((void**)&w1h, g_w1h);
    cudaGetSymbolAddress((void**)&w1l, g_w1l);
    cudaGetSymbolAddress((void**)&w2h, g_w2h);
    cudaGetSymbolAddress((void**)&w2l, g_w2l);

    const int gemm_smem = 2 * STAGEB;                      // 81920 B
    cudaFuncSetAttribute(hgemm3_kernel,
                         cudaFuncAttributeMaxDynamicSharedMemorySize, gemm_smem);
    cudaFuncSetAttribute(attn_kernel,
                         cudaFuncAttributeMaxDynamicSharedMemorySize, ATT_SMEM);

    const dim3 wt_blk(32, 8);
    const int n4_512  = MROWS * DIN / 4;
    const dim3 ggemm512(DIN / 128, MROWS / 128);
    const dim3 ggemm2048(DMID / 128, MROWS / 128);

    wtrans_kernel<<<dim3(DIN/32, DIN/32), wt_blk>>>(WQ, wqh, wql, DIN, DIN);
    cvt_split_kernel<<<n4_512/256, 256>>>(query, ahi, alo, n4_512);
    wtrans_kernel<<<dim3(DIN/32, DIN/32), wt_blk>>>(WK, wkh, wkl, DIN, DIN);
    cvt_split_kernel<<<n4_512/256, 256>>>(key, ath, atl, n4_512);
    hgemm3_kernel<<<ggemm512, 256, gemm_smem>>>(ahi, alo, wqh, wql,
                                                nullptr, qh, ql, DIN, DIN, 0, 1);
    hgemm3_kernel<<<ggemm512, 256, gemm_smem>>>(ath, atl, wkh, wkl,
                                                nullptr, kh, kl, DIN, DIN, 0, 1);
    wtrans_kernel<<<dim3(DIN/32, DIN/32), wt_blk>>>(WV, wvh, wvl, DIN, DIN);
    cvt_split_kernel<<<n4_512/256, 256>>>(value, ahi, alo, n4_512);
    hgemm3_kernel<<<ggemm512, 256, gemm_smem>>>(ahi, alo, wvh, wvl,
                                                Vp, nullptr, nullptr, DIN, DIN, 0, 0);
    vtrans_kernel<<<dim3(LL/32, DH/32, BB*NH), wt_blk>>>(Vp, vth, vtl);

    attn_kernel<<<dim3(LL/128, NH, BB), 256, ATT_SMEM>>>(
        qh, ql, kh, kl, vth, vtl, mask, ath, atl);

    wtrans_kernel<<<dim3(DIN/32, DIN/32), wt_blk>>>(WO, woh, wol, DIN, DIN);
    hgemm3_kernel<<<ggemm512, 256, gemm_smem>>>(ath, atl, woh, wol,
                                                tmp, nullptr, nullptr, DIN, DIN, 0, 0);
    ln_residual_kernel<<<MROWS, 128>>>(query, tmp, xa, qh, ql, 1);

    wtrans_kernel<<<dim3(DMID/32, DIN/32),  wt_blk>>>(W1, w1h, w1l, DIN, DMID);
    wtrans_kernel<<<dim3(DIN/32,  DMID/32), wt_blk>>>(W2, w2h, w2l, DMID, DIN);
    hgemm3_kernel<<<ggemm2048, 256, gemm_smem>>>(qh, ql, w1h, w1l,
                                                 nullptr, ahi, alo, DIN, DMID, 1, 1);
    hgemm3_kernel<<<ggemm512, 256, gemm_smem>>>(ahi, alo, w2h, w2l,
                                                tmp, nullptr, nullptr, DMID, DIN, 0, 0);
    ln_residual_kernel<<<MROWS, 128>>>(xa, tmp, out, nullptr, nullptr, 0);
}

// round 15
// speedup vs baseline: 1.0130x; 1.0130x over previous
#include <cuda_runtime.h>
#include <cuda_bf16.h>
#include <math.h>
#include <stdint.h>

// Problem constants
#define BB   4
#define LL   2048
#define NH   8
#define DH   64
#define DIN  512
#define DMID 2048
#define MROWS (BB*LL)    // 8192

// ---------------- scratch (__device__ globals; no allocation allowed) -------
__device__ float g_V  [MROWS * DIN];
__device__ float g_tmp[MROWS * DIN];
__device__ float g_xa [MROWS * DIN];

// split-bf16 buffers
__device__ __nv_bfloat16 g_ahi[MROWS * DMID];
__device__ __nv_bfloat16 g_alo[MROWS * DMID];
__device__ __nv_bfloat16 g_qh[MROWS * DIN], g_ql[MROWS * DIN];
__device__ __nv_bfloat16 g_kh[MROWS * DIN], g_kl[MROWS * DIN];
__device__ __nv_bfloat16 g_ath[MROWS * DIN], g_atl[MROWS * DIN];
__device__ __nv_bfloat16 g_vth[BB * NH * DH * LL];   // [bh][dim][key] hi
__device__ __nv_bfloat16 g_vtl[BB * NH * DH * LL];   // [bh][dim][key] lo
// transposed split-bf16 weights  [N, K]
__device__ __nv_bfloat16 g_wqh[DIN*DIN],  g_wql[DIN*DIN];
__device__ __nv_bfloat16 g_wkh[DIN*DIN],  g_wkl[DIN*DIN];
__device__ __nv_bfloat16 g_wvh[DIN*DIN],  g_wvl[DIN*DIN];
__device__ __nv_bfloat16 g_woh[DIN*DIN],  g_wol[DIN*DIN];
__device__ __nv_bfloat16 g_w1h[DMID*DIN], g_w1l[DMID*DIN];
__device__ __nv_bfloat16 g_w2h[DIN*DMID], g_w2l[DIN*DMID];

// ---------------- PTX helpers (compute_103-safe) ----------------------------
__device__ __forceinline__ uint32_t smem_u32(const void* p) {
    uint32_t a;
    asm("{ .reg .u64 t; cvta.to.shared.u64 t, %1; cvt.u32.u64 %0, t; }"
        : "=r"(a) : "l"(p));
    return a;
}
__device__ __forceinline__ void ldsm_x4(uint32_t* r, uint32_t addr) {
    asm volatile("ldmatrix.sync.aligned.m8n8.x4.shared.b16 {%0,%1,%2,%3}, [%4];"
        : "=r"(r[0]), "=r"(r[1]), "=r"(r[2]), "=r"(r[3]) : "r"(addr));
}
__device__ __forceinline__ void mma16816(float* d, const uint32_t* a,
                                         const uint32_t* b) {
    asm volatile("mma.sync.aligned.m16n8k16.row.col.f32.bf16.bf16.f32 "
        "{%0,%1,%2,%3}, {%4,%5,%6,%7}, {%8,%9}, {%0,%1,%2,%3};"
        : "+f"(d[0]), "+f"(d[1]), "+f"(d[2]), "+f"(d[3])
        : "r"(a[0]), "r"(a[1]), "r"(a[2]), "r"(a[3]), "r"(b[0]), "r"(b[1]));
}
#define CP_ASYNC16(dst, src) \
    asm volatile("cp.async.cg.shared.global [%0], [%1], 16;" :: "r"(dst), "l"(src))
#define CP_COMMIT() asm volatile("cp.async.commit_group;" ::: "memory")
#define CP_WAIT1()  asm volatile("cp.async.wait_group 1;" ::: "memory")
#define CP_WAIT0()  asm volatile("cp.async.wait_group 0;" ::: "memory")

__device__ __forceinline__ uint32_t pack2bf(float x0, float x1) {
    __nv_bfloat16 h0 = __float2bfloat16(x0);
    __nv_bfloat16 h1 = __float2bfloat16(x1);
    return ((uint32_t)__bfloat16_as_ushort(h1) << 16) | __bfloat16_as_ushort(h0);
}
__device__ __forceinline__ void split2(float x0, float x1,
                                       uint32_t& hi, uint32_t& lo) {
    __nv_bfloat16 h0 = __float2bfloat16(x0);
    __nv_bfloat16 h1 = __float2bfloat16(x1);
    hi = ((uint32_t)__bfloat16_as_ushort(h1) << 16) | __bfloat16_as_ushort(h0);
    lo = pack2bf(x0 - __bfloat162float(h0), x1 - __bfloat162float(h1));
}

// ---------------- split-bf16 HMMA GEMM (R5-validated mainloop) ---------------
#define KCH   32
#define RSTRB 80
#define OPB   (128 * RSTRB)
#define STAGEB (4 * OPB)
__global__ __launch_bounds__(256, 2) void hgemm3_kernel(
    const __nv_bfloat16* __restrict__ Ahi, const __nv_bfloat16* __restrict__ Alo,
    const __nv_bfloat16* __restrict__ Bh,  const __nv_bfloat16* __restrict__ Bl,
    float* __restrict__ C,
    __nv_bfloat16* __restrict__ Chi, __nv_bfloat16* __restrict__ Clo,
    int K, int N, int do_relu, int mode)
{
    extern __shared__ char smem[];
    const uint32_t sb = smem_u32(smem);
    const int tid  = threadIdx.x;
    const int wid  = tid >> 5;
    const int lane = tid & 31;
    const int wm   = wid >> 2;
    const int wn   = wid & 3;
    const int bx = blockIdx.x, by = blockIdx.y;

    const size_t aBase = (size_t)by * 128 * K;
    const size_t bBase = (size_t)bx * 128 * K;
    const __nv_bfloat16* tp[4] = { Ahi + aBase, Alo + aBase, Bh + bBase, Bl + bBase };

    const int nk = K / KCH;

    float acc[4][4][4];
    #pragma unroll
    for (int i = 0; i < 4; i++)
        #pragma unroll
        for (int j = 0; j < 4; j++)
            #pragma unroll
            for (int v = 0; v < 4; v++) acc[i][j][v] = 0.f;

    auto load_stage = [&](int kt, int stage) {
        const size_t koff = (size_t)kt * KCH;
        const uint32_t sbase = sb + stage * STAGEB;
        #pragma unroll
        for (int i = 0; i < 8; i++) {
            int idx = tid + i * 256;
            int op  = idx >> 9;
            int rem = idx & 511;
            int r   = rem >> 2;
            int s   = rem & 3;
            const __nv_bfloat16* src = tp[op] + (size_t)r * K + koff + s * 8;
            uint32_t dst = sbase + op * OPB + r * RSTRB + s * 16;
            CP_ASYNC16(dst, src);
        }
        CP_COMMIT();
    };

    load_stage(0, 0);

    const int a_m  = (lane & 15);
    const int a_kb = (lane >> 4) * 16;
    const int b_n  = (lane & 7) + ((lane >> 4) << 3);
    const int b_kb = ((lane >> 3) & 1) * 16;

    for (int kt = 0; kt < nk; kt++) {
        if (kt + 1 < nk) { load_stage(kt + 1, (kt + 1) & 1); CP_WAIT1(); }
        else             { CP_WAIT0(); }
        __syncthreads();

        const uint32_t st = sb + (kt & 1) * STAGEB;
        #pragma unroll
        for (int ks = 0; ks < 2; ks++) {
            const uint32_t kofs = ks * 32;

            uint32_t bh[2][4], bl[2][4];
            #pragma unroll
            for (int np = 0; np < 2; np++) {
                int n = wn * 32 + np * 16 + b_n;
                ldsm_x4(bh[np], st + 2 * OPB + n * RSTRB + kofs + b_kb);
                ldsm_x4(bl[np], st + 3 * OPB + n * RSTRB + kofs + b_kb);
            }

            uint32_t af[4][4];
            #pragma unroll
            for (int mt = 0; mt < 4; mt++) {
                int m = wm * 64 + mt * 16 + a_m;
                ldsm_x4(af[mt], st + 0 * OPB + m * RSTRB + kofs + a_kb);
            }
            #pragma unroll
            for (int mt = 0; mt < 4; mt++)
                #pragma unroll
                for (int nt = 0; nt < 4; nt++) {
                    mma16816(acc[mt][nt], af[mt], &bh[nt >> 1][(nt & 1) * 2]);
                    mma16816(acc[mt][nt], af[mt], &bl[nt >> 1][(nt & 1) * 2]);
                }
            #pragma unroll
            for (int mt = 0; mt < 4; mt++) {
                int m = wm * 64 + mt * 16 + a_m;
                ldsm_x4(af[mt], st + 1 * OPB + m * RSTRB + kofs + a_kb);
            }
            #pragma unroll
            for (int mt = 0; mt < 4; mt++)
                #pragma unroll
                for (int nt = 0; nt < 4; nt++)
                    mma16816(acc[mt][nt], af[mt], &bh[nt >> 1][(nt & 1) * 2]);
        }
        __syncthreads();
    }

    const int rbase = by * 128 + wm * 64 + (lane >> 2);
    const int cbase = bx * 128 + wn * 32 + (lane & 3) * 2;
    #pragma unroll
    for (int mt = 0; mt < 4; mt++)
        #pragma unroll
        for (int nt = 0; nt < 4; nt++) {
            float* d = acc[mt][nt];
            if (do_relu) {
                d[0] = fmaxf(d[0], 0.f); d[1] = fmaxf(d[1], 0.f);
                d[2] = fmaxf(d[2], 0.f); d[3] = fmaxf(d[3], 0.f);
            }
            int r = rbase + mt * 16;
            int c = cbase + nt * 8;
            if (mode == 0) {
                *(float2*)(C + (size_t)r * N + c)       = make_float2(d[0], d[1]);
                *(float2*)(C + (size_t)(r + 8) * N + c) = make_float2(d[2], d[3]);
            } else {
                uint32_t h0, l0, h1, l1;
                split2(d[0], d[1], h0, l0);
                split2(d[2], d[3], h1, l1);
                *(uint32_t*)(Chi + (size_t)r * N + c)       = h0;
                *(uint32_t*)(Clo + (size_t)r * N + c)       = l0;
                *(uint32_t*)(Chi + (size_t)(r + 8) * N + c) = h1;
                *(uint32_t*)(Clo + (size_t)(r + 8) * N + c) = l1;
            }
        }
}

// ---------------- fp32 -> (hi, lo) bf16 split --------------------------------
__global__ __launch_bounds__(256) void cvt_split_kernel(
    const float* __restrict__ x, __nv_bfloat16* __restrict__ hi,
    __nv_bfloat16* __restrict__ lo, int n4)
{
    int i = blockIdx.x * 256 + threadIdx.x;
    if (i >= n4) return;
    float4 v = ((const float4*)x)[i];
    uint32_t h0, l0, h1, l1;
    split2(v.x, v.y, h0, l0);
    split2(v.z, v.w, h1, l1);
    uint32_t* hp = (uint32_t*)hi;
    uint32_t* lp = (uint32_t*)lo;
    hp[2*i]   = h0;
    hp[2*i+1] = h1;
    lp[2*i]   = l0;
    lp[2*i+1] = l1;
}

// ---------------- weight transpose + split -----------------------------------
__global__ __launch_bounds__(256) void wtrans_kernel(
    const float* __restrict__ W, __nv_bfloat16* __restrict__ Thi,
    __nv_bfloat16* __restrict__ Tlo, int K, int N)
{
    __shared__ float t[32][33];
    const int tx = threadIdx.x, ty = threadIdx.y;
    const int n0 = blockIdx.x * 32, k0 = blockIdx.y * 32;
    #pragma unroll
    for (int i = 0; i < 4; i++)
        t[ty + 8*i][tx] = W[(size_t)(k0 + ty + 8*i) * N + n0 + tx];
    __syncthreads();
    #pragma unroll
    for (int i = 0; i < 4; i++) {
        float v = t[tx][ty + 8*i];
        __nv_bfloat16 h = __float2bfloat16(v);
        __nv_bfloat16 l = __float2bfloat16(v - __bfloat162float(h));
        size_t o = (size_t)(n0 + ty + 8*i) * K + k0 + tx;
        Thi[o] = h;
        Tlo[o] = l;
    }
}

// ---------------- V transpose -> bf16 hi/lo [bh][dim][key] -------------------
__global__ __launch_bounds__(256) void vtrans_kernel(
    const float* __restrict__ V, __nv_bfloat16* __restrict__ Vth,
    __nv_bfloat16* __restrict__ Vtl)
{
    __shared__ float t[32][33];
    const int tx = threadIdx.x, ty = threadIdx.y;   // block (32, 8)
    const int l0 = blockIdx.x * 32;
    const int d0 = blockIdx.y * 32;
    const int bh = blockIdx.z;                      // b*NH + h
    const int b  = bh >> 3, h = bh & 7;
    #pragma unroll
    for (int i = 0; i < 4; i++)
        t[ty + 8*i][tx] = V[(size_t)(b * LL + l0 + ty + 8*i) * DIN + h * DH + d0 + tx];
    __syncthreads();
    #pragma unroll
    for (int i = 0; i < 4; i++) {
        float v = t[tx][ty + 8*i];                  // (l = l0+tx, d = d0+ty+8i)
        __nv_bfloat16 hh = __float2bfloat16(v);
        __nv_bfloat16 lo = __float2bfloat16(v - __bfloat162float(hh));
        size_t o = ((size_t)bh * DH + d0 + ty + 8*i) * LL + l0 + tx;
        Vth[o] = hh;
        Vtl[o] = lo;
    }
}

// ---------------- HMMA flash attention: 128-q tiles, 512 threads -------------
// grid (LL/128, NH, BB), 512 threads = 16 warps.
// Score persona (R8-validated): warp w -> rows (w&7)*16, keys (w>>3)*32.
// PV persona (R9-validated):    warp w -> rows (w&7)*16, dims (w>>3)*32.
// Softmax: 32x16 thread grid, 4 rows/thread (R3-validated loop).
// K single-buf, V double-buf, mask aliased into Ss; load-over-PV pipeline.
#define SRB  144                      // bf16 tile row stride (bytes)
#define FSTR 68                       // fp32 tile stride (floats)
#define S_QH 0                        // 128 rows
#define S_QL (S_QH + 128 * SRB)       // 18432
#define S_KH (S_QL + 128 * SRB)       // 36864 (64 rows)
#define S_KL (S_KH + 64 * SRB)        // 46080
#define S_V0 (S_KL + 64 * SRB)        // 55296 (2 bufs x (hi 9216 + lo 9216))
#define S_PH (S_V0 + 4 * 64 * SRB)    // 92160 (128 rows)
#define S_PL (S_PH + 128 * SRB)       // 110592
#define S_S  (S_PL + 128 * SRB)       // 129024 (fp32 128x68; mask target)
#define S_AR (S_S + 128 * FSTR * 4)   // 163840 (alpha, 128 floats)
#define S_LR (S_AR + 512)             // 164352 (l_run, 128 floats)
#define ATT_SMEM (S_LR + 512)         // 164864
__global__ __launch_bounds__(512) void attn_kernel(
    const __nv_bfloat16* __restrict__ Qh, const __nv_bfloat16* __restrict__ Ql,
    const __nv_bfloat16* __restrict__ Kh, const __nv_bfloat16* __restrict__ Kl,
    const __nv_bfloat16* __restrict__ Vth, const __nv_bfloat16* __restrict__ Vtl,
    const float* __restrict__ mask,
    __nv_bfloat16* __restrict__ Oh, __nv_bfloat16* __restrict__ Ol)
{
    extern __shared__ char smem[];
    const uint32_t sb = smem_u32(smem);
    float* Ss   = (float*)(smem + S_S);
    float* arow = (float*)(smem + S_AR);
    float* lrow = (float*)(smem + S_LR);

    const int qt = blockIdx.x;
    const int h  = blockIdx.y;
    const int b  = blockIdx.z;
    const int bh = b * NH + h;

    const int tid  = threadIdx.x;
    const int wid  = tid >> 5;
    const int lane = tid & 31;
    const int tx   = tid & 15;
    const int ty   = tid >> 4;        // 0..31
    const int r0   = ty * 4;          // rows 0..124
    const int c0   = tx * 4;

    const size_t krow0base = (size_t)b * LL;
    const size_t vrow0 = (size_t)bh * DH;
    const float* maskb = mask + ((size_t)b * LL + qt * 128) * LL;

    auto load_kv_mask = [&](int kt) {
        const size_t krow0 = krow0base + kt * 64;
        const uint32_t svb = sb + S_V0 + (kt & 1) * 18432;
        #pragma unroll
        for (int i = 0; i < 2; i++) {
            int idx = tid + i * 512;               // 0..1023
            int op  = idx >> 9;
            int rem = idx & 511;
            int r   = rem >> 3;
            int seg = rem & 7;
            const __nv_bfloat16* src =
                (op ? Kl : Kh) + (krow0 + r) * DIN + h * DH + seg * 8;
            CP_ASYNC16(sb + (op ? S_KL : S_KH) + r * SRB + seg * 16, src);
        }
        #pragma unroll
        for (int i = 0; i < 2; i++) {
            int idx = tid + i * 512;
            int op  = idx >> 9;                    // 0: Vth, 1: Vtl
            int rem = idx & 511;
            int r   = rem >> 3;                    // dim 0..63
            int seg = rem & 7;
            const __nv_bfloat16* src =
                (op ? Vtl : Vth) + (vrow0 + r) * LL + kt * 64 + seg * 8;
            CP_ASYNC16(svb + op * 9216 + r * SRB + seg * 16, src);
        }
        // mask tile [128][64] fp32 into Ss (FSTR-padded rows)
        #pragma unroll
        for (int i = 0; i < 4; i++) {
            int idx = tid + i * 512;               // 0..2047
            int r   = idx >> 4;
            int s   = idx & 15;
            const float* src = maskb + (size_t)r * LL + kt * 64 + s * 4;
            CP_ASYNC16(sb + S_S + r * (FSTR * 4) + s * 16, src);
        }
        CP_COMMIT();
    };

    // ---- prologue: Q (128 rows) + tile 0 in one group ----
    {
        const size_t qrow0 = (size_t)(b * LL + qt * 128);
        #pragma unroll
        for (int i = 0; i < 4; i++) {
            int idx = tid + i * 512;          // 0..2047
            int op  = idx >> 10;              // 0: Qh, 1: Ql
            int rem = idx & 1023;
            int r   = rem >> 3;
            int seg = rem & 7;
            const __nv_bfloat16* src =
                (op ? Ql : Qh) + (qrow0 + r) * DIN + h * DH + seg * 8;
            CP_ASYNC16(sb + (op ? S_QL : S_QH) + r * SRB + seg * 16, src);
        }
        load_kv_mask(0);        // commits (Q included in same group)
        CP_WAIT0();
    }
    __syncthreads();

    // HMMA lane addressing (R5/R8-validated)
    const int a_m  = (lane & 15);
    const int a_kb = (lane >> 4) * 16;
    const int b_n  = (lane & 7) + ((lane >> 4) << 3);
    const int b_kb = ((lane >> 3) & 1) * 16;
    const int qr = (wid & 7) * 16;     // score persona: warp's 16 query rows
    const int kc = (wid >> 3) * 32;    // score persona: warp's 32 key cols
    const int wm = wid & 7;            // PV persona: 16 query rows
    const int wn = wid >> 3;           // PV persona: 32 output dims
    const int rl0 = wm * 16 + (lane >> 2);

    // ---- hoist Q fragments ----
    uint32_t qfh[4][4], qfl[4][4];
    #pragma unroll
    for (int k4 = 0; k4 < 4; k4++) {
        uint32_t ro = (qr + a_m) * SRB + k4 * 32 + a_kb;
        ldsm_x4(qfh[k4], sb + S_QH + ro);
        ldsm_x4(qfl[k4], sb + S_QL + ro);
    }

    float m_run[4], l_run[4];
    #pragma unroll
    for (int i = 0; i < 4; i++) { m_run[i] = -1.0e30f; l_run[i] = 0.f; }

    float oacc[4][4];
    #pragma unroll
    for (int j = 0; j < 4; j++)
        #pragma unroll
        for (int v = 0; v < 4; v++) oacc[j][v] = 0.f;

    const int nkt = LL / 64;
    for (int kt = 0; kt < nkt; kt++) {
        // ---- HMMA scores (R8-validated): warp -> 16 q rows x 32 keys ----
        {
            float sc[4][4];
            #pragma unroll
            for (int j = 0; j < 4; j++)
                #pragma unroll
                for (int v = 0; v < 4; v++) sc[j][v] = 0.f;

            #pragma unroll
            for (int k4 = 0; k4 < 4; k4++) {
                uint32_t bhf[2][4], blf[2][4];
                #pragma unroll
                for (int np = 0; np < 2; np++) {
                    uint32_t rk = (kc + np * 16 + b_n) * SRB + k4 * 32 + b_kb;
                    ldsm_x4(bhf[np], sb + S_KH + rk);
                    ldsm_x4(blf[np], sb + S_KL + rk);
                }
                #pragma unroll
                for (int j = 0; j < 4; j++) {
                    mma16816(sc[j], qfh[k4], &bhf[j >> 1][(j & 1) * 2]);
                    mma16816(sc[j], qfh[k4], &blf[j >> 1][(j & 1) * 2]);
                    mma16816(sc[j], qfl[k4], &bhf[j >> 1][(j & 1) * 2]);
                }
            }

            const int sr0 = qr + (lane >> 2);
            #pragma unroll
            for (int j = 0; j < 4; j++) {
                int col = kc + j * 8 + 2 * (lane & 3);
                float2 mk0 = *(const float2*)&Ss[sr0 * FSTR + col];       // mask
                float2 mk1 = *(const float2*)&Ss[(sr0 + 8) * FSTR + col];
                *(float2*)&Ss[sr0 * FSTR + col] =
                    make_float2(fmaf(sc[j][0], 0.125f, mk0.x),
                                fmaf(sc[j][1], 0.125f, mk0.y));
                *(float2*)&Ss[(sr0 + 8) * FSTR + col] =
                    make_float2(fmaf(sc[j][2], 0.125f, mk1.x),
                                fmaf(sc[j][3], 0.125f, mk1.y));
            }
        }
        __syncthreads();

        // ---- fp32 online softmax (R3-validated); 32x16 grid, 4 rows/thread ----
        {
            float s[4][4];
            #pragma unroll
            for (int i = 0; i < 4; i++)
                #pragma unroll
                for (int j = 0; j < 4; j++)
                    s[i][j] = Ss[(r0 + i) * FSTR + c0 + j];

            #pragma unroll
            for (int i = 0; i < 4; i++) {
                float ml = fmaxf(fmaxf(s[i][0], s[i][1]), fmaxf(s[i][2], s[i][3]));
                #pragma unroll
                for (int off = 1; off < 16; off <<= 1)
                    ml = fmaxf(ml, __shfl_xor_sync(0xffffffffu, ml, off));

                float mnew  = fmaxf(m_run[i], ml);
                float alpha = __expf(m_run[i] - mnew);
                m_run[i] = mnew;

                float lsum = 0.f;
                #pragma unroll
                for (int j = 0; j < 4; j++) {
                    float p = __expf(s[i][j] - mnew);
                    s[i][j] = p;
                    lsum += p;
                }
                #pragma unroll
                for (int off = 1; off < 16; off <<= 1)
                    lsum += __shfl_xor_sync(0xffffffffu, lsum, off);
                l_run[i] = l_run[i] * alpha + lsum;

                if (tx == 0) arow[r0 + i] = alpha;

                uint32_t h0, l0p, h1, l1p;
                split2(s[i][0], s[i][1], h0, l0p);
                split2(s[i][2], s[i][3], h1, l1p);
                uint32_t off0 = (r0 + i) * SRB + c0 * 2;
                *(uint32_t*)(smem + S_PH + off0)     = h0;
                *(uint32_t*)(smem + S_PH + off0 + 4) = h1;
                *(uint32_t*)(smem + S_PL + off0)     = l0p;
                *(uint32_t*)(smem + S_PL + off0 + 4) = l1p;
            }
        }
        __syncthreads();
        // K free, Ss free, V[(kt+1)&1] free -> prefetch next tile over PV
        if (kt + 1 < nkt) load_kv_mask(kt + 1);

        // ---- PV HMMA (R9-validated): warp -> 16 q rows x 32 dims ----
        {
            const uint32_t svb = sb + S_V0 + (kt & 1) * 18432;
            float a0 = arow[rl0];
            float a1 = arow[rl0 + 8];
            #pragma unroll
            for (int j = 0; j < 4; j++) {
                oacc[j][0] *= a0; oacc[j][1] *= a0;
                oacc[j][2] *= a1; oacc[j][3] *= a1;
            }

            #pragma unroll
            for (int k4 = 0; k4 < 4; k4++) {
                uint32_t aph[4], apl[4];
                uint32_t ro = (wm * 16 + a_m) * SRB + k4 * 32 + a_kb;
                ldsm_x4(aph, sb + S_PH + ro);
                ldsm_x4(apl, sb + S_PL + ro);
                uint32_t bvh[2][4], bvl[2][4];
                #pragma unroll
                for (int np = 0; np < 2; np++) {
                    uint32_t rk = (wn * 32 + np * 16 + b_n) * SRB + k4 * 32 + b_kb;
                    ldsm_x4(bvh[np], svb + rk);
                    ldsm_x4(bvl[np], svb + 9216 + rk);
                }
                #pragma unroll
                for (int j = 0; j < 4; j++) {
                    mma16816(oacc[j], aph, &bvh[j >> 1][(j & 1) * 2]);
                    mma16816(oacc[j], aph, &bvl[j >> 1][(j & 1) * 2]);
                    mma16816(oacc[j], apl, &bvh[j >> 1][(j & 1) * 2]);
                }
            }
        }

        if (kt + 1 < nkt) CP_WAIT0();
        __syncthreads();
    }

    // ---- publish l_run, split-bf16 epilogue ----
    if (tx == 0) {
        #pragma unroll
        for (int i = 0; i < 4; i++) lrow[r0 + i] = l_run[i];
    }
    __syncthreads();

    const float inv0 = 1.f / lrow[rl0];
    const float inv1 = 1.f / lrow[rl0 + 8];
    const size_t o0 = ((size_t)(b * LL + qt * 128 + rl0)) * DIN + h * DH
                    + wn * 32 + 2 * (lane & 3);
    const size_t o1 = o0 + 8 * DIN;
    #pragma unroll
    for (int j = 0; j < 4; j++) {
        uint32_t h0, l0p, h1, l1p;
        split2(oacc[j][0] * inv0, oacc[j][1] * inv0, h0, l0p);
        split2(oacc[j][2] * inv1, oacc[j][3] * inv1, h1, l1p);
        *(uint32_t*)(Oh + o0 + 8 * j) = h0;
        *(uint32_t*)(Ol + o0 + 8 * j) = l0p;
        *(uint32_t*)(Oh + o1 + 8 * j) = h1;
        *(uint32_t*)(Ol + o1 + 8 * j) = l1p;
    }
}

// ---------------- residual + LayerNorm (optional split output) ---------------
__global__ __launch_bounds__(128) void ln_residual_kernel(
    const float* __restrict__ x, const float* __restrict__ y,
    float* __restrict__ o,
    __nv_bfloat16* __restrict__ ohi, __nv_bfloat16* __restrict__ olo,
    int emit_split)
{
    const int row = blockIdx.x;
    const int t   = threadIdx.x;
    const float* xr = x + (size_t)row * DIN;
    const float* yr = y + (size_t)row * DIN;

    float v[4];
    float s = 0.f, s2 = 0.f;
    #pragma unroll
    for (int i = 0; i < 4; i++) {
        float a = xr[t + 128 * i] + yr[t + 128 * i];
        v[i] = a;
        s  += a;
        s2 += a * a;
    }
    #pragma unroll
    for (int off = 16; off; off >>= 1) {
        s  += __shfl_xor_sync(0xffffffffu, s,  off);
        s2 += __shfl_xor_sync(0xffffffffu, s2, off);
    }
    __shared__ float ss[4], ss2[4];
    if ((t & 31) == 0) { ss[t >> 5] = s; ss2[t >> 5] = s2; }
    __syncthreads();
    s  = ss[0]  + ss[1]  + ss[2]  + ss[3];
    s2 = ss2[0] + ss2[1] + ss2[2] + ss2[3];

    const float mean = s * (1.f / DIN);
    const float var  = s2 * (1.f / DIN) - mean * mean;
    const float r    = rsqrtf(var + 1e-5f);

    float* orow = o + (size_t)row * DIN;
    #pragma unroll
    for (int i = 0; i < 4; i++) {
        float val = (v[i] - mean) * r;
        orow[t + 128 * i] = val;
        if (emit_split) {
            __nv_bfloat16 hh = __float2bfloat16(val);
            ohi[(size_t)row * DIN + t + 128 * i] = hh;
            olo[(size_t)row * DIN + t + 128 * i] =
                __float2bfloat16(val - __bfloat162float(hh));
        }
    }
}

// ---------------- launch -----------------------------------------------------
extern "C" void kernel_launch(void* const* d_in, const int* in_sizes, int n_in,
                              void* d_out, int out_size)
{
    const float* query = (const float*)d_in[0];
    const float* key   = (const float*)d_in[1];
    const float* value = (const float*)d_in[2];
    const float* mask  = (const float*)d_in[3];
    const float* WQ    = (const float*)d_in[4];
    const float* WK    = (const float*)d_in[5];
    const float* WV    = (const float*)d_in[6];
    const float* WO    = (const float*)d_in[7];
    const float* W1    = (const float*)d_in[8];
    const float* W2    = (const float*)d_in[9];
    float* out = (float*)d_out;

    float *Vp, *tmp, *xa;
    cudaGetSymbolAddress((void**)&Vp,  g_V);
    cudaGetSymbolAddress((void**)&tmp, g_tmp);
    cudaGetSymbolAddress((void**)&xa,  g_xa);

    __nv_bfloat16 *ahi, *alo, *qh, *ql, *kh, *kl, *ath, *atl, *vth, *vtl;
    __nv_bfloat16 *wqh, *wql, *wkh, *wkl, *wvh, *wvl;
    __nv_bfloat16 *woh, *wol, *w1h, *w1l, *w2h, *w2l;
    cudaGetSymbolAddress((void**)&ahi, g_ahi);
    cudaGetSymbolAddress((void**)&alo, g_alo);
    cudaGetSymbolAddress((void**)&qh,  g_qh);
    cudaGetSymbolAddress((void**)&ql,  g_ql);
    cudaGetSymbolAddress((void**)&kh,  g_kh);
    cudaGetSymbolAddress((void**)&kl,  g_kl);
    cudaGetSymbolAddress((void**)&ath, g_ath);
    cudaGetSymbolAddress((void**)&atl, g_atl);
    cudaGetSymbolAddress((void**)&vth, g_vth);
    cudaGetSymbolAddress((void**)&vtl, g_vtl);
    cudaGetSymbolAddress((void**)&wqh, g_wqh);
    cudaGetSymbolAddress((void**)&wql, g_wql);
    cudaGetSymbolAddress((void**)&wkh, g_wkh);
    cudaGetSymbolAddress((void**)&wkl, g_wkl);
    cudaGetSymbolAddress((void**)&wvh, g_wvh);
    cudaGetSymbolAddress((void**)&wvl, g_wvl);
    cudaGetSymbolAddress((void**)&woh, g_woh);
    cudaGetSymbolAddress((void**)&wol, g_wol);
    cudaGetSymbolAddress((void**)&w1h, g_w1h);
    cudaGetSymbolAddress((void**)&w1l, g_w1l);
    cudaGetSymbolAddress((void**)&w2h, g_w2h);
    cudaGetSymbolAddress((void**)&w2l, g_w2l);

    const int gemm_smem = 2 * STAGEB;                      // 81920 B
    cudaFuncSetAttribute(hgemm3_kernel,
                         cudaFuncAttributeMaxDynamicSharedMemorySize, gemm_smem);
    cudaFuncSetAttribute(attn_kernel,
                         cudaFuncAttributeMaxDynamicSharedMemorySize, ATT_SMEM);

    const dim3 wt_blk(32, 8);
    const int n4_512  = MROWS * DIN / 4;
    const dim3 ggemm512(DIN / 128, MROWS / 128);
    const dim3 ggemm2048(DMID / 128, MROWS / 128);

    wtrans_kernel<<<dim3(DIN/32, DIN/32), wt_blk>>>(WQ, wqh, wql, DIN, DIN);
    cvt_split_kernel<<<n4_512/256, 256>>>(query, ahi, alo, n4_512);
    wtrans_kernel<<<dim3(DIN/32, DIN/32), wt_blk>>>(WK, wkh, wkl, DIN, DIN);
    cvt_split_kernel<<<n4_512/256, 256>>>(key, ath, atl, n4_512);
    hgemm3_kernel<<<ggemm512, 256, gemm_smem>>>(ahi, alo, wqh, wql,
                                                nullptr, qh, ql, DIN, DIN, 0, 1);
    hgemm3_kernel<<<ggemm512, 256, gemm_smem>>>(ath, atl, wkh, wkl,
                                                nullptr, kh, kl, DIN, DIN, 0, 1);
    wtrans_kernel<<<dim3(DIN/32, DIN/32), wt_blk>>>(WV, wvh, wvl, DIN, DIN);
    cvt_split_kernel<<<n4_512/256, 256>>>(value, ahi, alo, n4_512);
    hgemm3_kernel<<<ggemm512, 256, gemm_smem>>>(ahi, alo, wvh, wvl,
                                                Vp, nullptr, nullptr, DIN, DIN, 0, 0);
    vtrans_kernel<<<dim3(LL/32, DH/32, BB*NH), wt_blk>>>(Vp, vth, vtl);

    attn_kernel<<<dim3(LL/128, NH, BB), 512, ATT_SMEM>>>(
        qh, ql, kh, kl, vth, vtl, mask, ath, atl);

    wtrans_kernel<<<dim3(DIN/32, DIN/32), wt_blk>>>(WO, woh, wol, DIN, DIN);
    hgemm3_kernel<<<ggemm512, 256, gemm_smem>>>(ath, atl, woh, wol,
                                                tmp, nullptr, nullptr, DIN, DIN, 0, 0);
    ln_residual_kernel<<<MROWS, 128>>>(query, tmp, xa, qh, ql, 1);

    wtrans_kernel<<<dim3(DMID/32, DIN/32),  wt_blk>>>(W1, w1h, w1l, DIN, DMID);
    wtrans_kernel<<<dim3(DIN/32,  DMID/32), wt_blk>>>(W2, w2h, w2l, DMID, DIN);
    hgemm3_kernel<<<ggemm2048, 256, gemm_smem>>>(qh, ql, w1h, w1l,
                                                 nullptr, ahi, alo, DIN, DMID, 1, 1);
    hgemm3_kernel<<<ggemm512, 256, gemm_smem>>>(ahi, alo, w2h, w2l,
                                                tmp, nullptr, nullptr, DMID, DIN, 0, 0);
    ln_residual_kernel<<<MROWS, 128>>>(xa, tmp, out, nullptr, nullptr, 0);
}

// round 16
// speedup vs baseline: 1.1140x; 1.0996x over previous
#include <cuda_runtime.h>
#include <cuda_bf16.h>
#include <math.h>
#include <stdint.h>

// Problem constants
#define BB   4
#define LL   2048
#define NH   8
#define DH   64
#define DIN  512
#define DMID 2048
#define MROWS (BB*LL)    // 8192

// ---------------- scratch (__device__ globals; no allocation allowed) -------
__device__ float g_V  [MROWS * DIN];
__device__ float g_tmp[MROWS * DIN];
__device__ float g_xa [MROWS * DIN];

// split-bf16 buffers
__device__ __nv_bfloat16 g_ahi[MROWS * DMID];
__device__ __nv_bfloat16 g_alo[MROWS * DMID];
__device__ __nv_bfloat16 g_qh[MROWS * DIN], g_ql[MROWS * DIN];
__device__ __nv_bfloat16 g_kh[MROWS * DIN], g_kl[MROWS * DIN];
__device__ __nv_bfloat16 g_vh[MROWS * DIN], g_vl[MROWS * DIN];
__device__ __nv_bfloat16 g_ath[MROWS * DIN], g_atl[MROWS * DIN];
__device__ __nv_bfloat16 g_vth[BB * NH * DH * LL];   // [bh][dim][key] hi
__device__ __nv_bfloat16 g_vtl[BB * NH * DH * LL];   // [bh][dim][key] lo
// transposed split-bf16 weights  [N, K]
__device__ __nv_bfloat16 g_wqh[DIN*DIN],  g_wql[DIN*DIN];
__device__ __nv_bfloat16 g_wkh[DIN*DIN],  g_wkl[DIN*DIN];
__device__ __nv_bfloat16 g_wvh[DIN*DIN],  g_wvl[DIN*DIN];
__device__ __nv_bfloat16 g_woh[DIN*DIN],  g_wol[DIN*DIN];
__device__ __nv_bfloat16 g_w1h[DMID*DIN], g_w1l[DMID*DIN];
__device__ __nv_bfloat16 g_w2h[DIN*DMID], g_w2l[DIN*DMID];

// ---------------- PTX helpers (compute_103-safe) ----------------------------
__device__ __forceinline__ uint32_t smem_u32(const void* p) {
    uint32_t a;
    asm("{ .reg .u64 t; cvta.to.shared.u64 t, %1; cvt.u32.u64 %0, t; }"
        : "=r"(a) : "l"(p));
    return a;
}
__device__ __forceinline__ void ldsm_x4(uint32_t* r, uint32_t addr) {
    asm volatile("ldmatrix.sync.aligned.m8n8.x4.shared.b16 {%0,%1,%2,%3}, [%4];"
        : "=r"(r[0]), "=r"(r[1]), "=r"(r[2]), "=r"(r[3]) : "r"(addr));
}
__device__ __forceinline__ void mma16816(float* d, const uint32_t* a,
                                         const uint32_t* b) {
    asm volatile("mma.sync.aligned.m16n8k16.row.col.f32.bf16.bf16.f32 "
        "{%0,%1,%2,%3}, {%4,%5,%6,%7}, {%8,%9}, {%0,%1,%2,%3};"
        : "+f"(d[0]), "+f"(d[1]), "+f"(d[2]), "+f"(d[3])
        : "r"(a[0]), "r"(a[1]), "r"(a[2]), "r"(a[3]), "r"(b[0]), "r"(b[1]));
}
#define CP_ASYNC16(dst, src) \
    asm volatile("cp.async.cg.shared.global [%0], [%1], 16;" :: "r"(dst), "l"(src))
#define CP_COMMIT() asm volatile("cp.async.commit_group;" ::: "memory")
#define CP_WAIT1()  asm volatile("cp.async.wait_group 1;" ::: "memory")
#define CP_WAIT0()  asm volatile("cp.async.wait_group 0;" ::: "memory")

__device__ __forceinline__ uint32_t pack2bf(float x0, float x1) {
    __nv_bfloat16 h0 = __float2bfloat16(x0);
    __nv_bfloat16 h1 = __float2bfloat16(x1);
    return ((uint32_t)__bfloat16_as_ushort(h1) << 16) | __bfloat16_as_ushort(h0);
}
__device__ __forceinline__ void split2(float x0, float x1,
                                       uint32_t& hi, uint32_t& lo) {
    __nv_bfloat16 h0 = __float2bfloat16(x0);
    __nv_bfloat16 h1 = __float2bfloat16(x1);
    hi = ((uint32_t)__bfloat16_as_ushort(h1) << 16) | __bfloat16_as_ushort(h0);
    lo = pack2bf(x0 - __bfloat162float(h0), x1 - __bfloat162float(h1));
}

// ---------------- split-bf16 HMMA GEMM (R5-validated mainloop) ---------------
#define KCH   32
#define RSTRB 80
#define OPB   (128 * RSTRB)
#define STAGEB (4 * OPB)
__global__ __launch_bounds__(256, 2) void hgemm3_kernel(
    const __nv_bfloat16* __restrict__ Ahi, const __nv_bfloat16* __restrict__ Alo,
    const __nv_bfloat16* __restrict__ Bh,  const __nv_bfloat16* __restrict__ Bl,
    float* __restrict__ C,
    __nv_bfloat16* __restrict__ Chi, __nv_bfloat16* __restrict__ Clo,
    int K, int N, int do_relu, int mode)
{
    extern __shared__ char smem[];
    const uint32_t sb = smem_u32(smem);
    const int tid  = threadIdx.x;
    const int wid  = tid >> 5;
    const int lane = tid & 31;
    const int wm   = wid >> 2;
    const int wn   = wid & 3;
    const int bx = blockIdx.x, by = blockIdx.y;

    const size_t aBase = (size_t)by * 128 * K;
    const size_t bBase = (size_t)bx * 128 * K;
    const __nv_bfloat16* tp[4] = { Ahi + aBase, Alo + aBase, Bh + bBase, Bl + bBase };

    const int nk = K / KCH;

    float acc[4][4][4];
    #pragma unroll
    for (int i = 0; i < 4; i++)
        #pragma unroll
        for (int j = 0; j < 4; j++)
            #pragma unroll
            for (int v = 0; v < 4; v++) acc[i][j][v] = 0.f;

    auto load_stage = [&](int kt, int stage) {
        const size_t koff = (size_t)kt * KCH;
        const uint32_t sbase = sb + stage * STAGEB;
        #pragma unroll
        for (int i = 0; i < 8; i++) {
            int idx = tid + i * 256;
            int op  = idx >> 9;
            int rem = idx & 511;
            int r   = rem >> 2;
            int s   = rem & 3;
            const __nv_bfloat16* src = tp[op] + (size_t)r * K + koff + s * 8;
            uint32_t dst = sbase + op * OPB + r * RSTRB + s * 16;
            CP_ASYNC16(dst, src);
        }
        CP_COMMIT();
    };

    load_stage(0, 0);

    const int a_m  = (lane & 15);
    const int a_kb = (lane >> 4) * 16;
    const int b_n  = (lane & 7) + ((lane >> 4) << 3);
    const int b_kb = ((lane >> 3) & 1) * 16;

    for (int kt = 0; kt < nk; kt++) {
        if (kt + 1 < nk) { load_stage(kt + 1, (kt + 1) & 1); CP_WAIT1(); }
        else             { CP_WAIT0(); }
        __syncthreads();

        const uint32_t st = sb + (kt & 1) * STAGEB;
        #pragma unroll
        for (int ks = 0; ks < 2; ks++) {
            const uint32_t kofs = ks * 32;

            uint32_t bh[2][4], bl[2][4];
            #pragma unroll
            for (int np = 0; np < 2; np++) {
                int n = wn * 32 + np * 16 + b_n;
                ldsm_x4(bh[np], st + 2 * OPB + n * RSTRB + kofs + b_kb);
                ldsm_x4(bl[np], st + 3 * OPB + n * RSTRB + kofs + b_kb);
            }

            uint32_t af[4][4];
            #pragma unroll
            for (int mt = 0; mt < 4; mt++) {
                int m = wm * 64 + mt * 16 + a_m;
                ldsm_x4(af[mt], st + 0 * OPB + m * RSTRB + kofs + a_kb);
            }
            #pragma unroll
            for (int mt = 0; mt < 4; mt++)
                #pragma unroll
                for (int nt = 0; nt < 4; nt++) {
                    mma16816(acc[mt][nt], af[mt], &bh[nt >> 1][(nt & 1) * 2]);
                    mma16816(acc[mt][nt], af[mt], &bl[nt >> 1][(nt & 1) * 2]);
                }
            #pragma unroll
            for (int mt = 0; mt < 4; mt++) {
                int m = wm * 64 + mt * 16 + a_m;
                ldsm_x4(af[mt], st + 1 * OPB + m * RSTRB + kofs + a_kb);
            }
            #pragma unroll
            for (int mt = 0; mt < 4; mt++)
                #pragma unroll
                for (int nt = 0; nt < 4; nt++)
                    mma16816(acc[mt][nt], af[mt], &bh[nt >> 1][(nt & 1) * 2]);
        }
        __syncthreads();
    }

    const int rbase = by * 128 + wm * 64 + (lane >> 2);
    const int cbase = bx * 128 + wn * 32 + (lane & 3) * 2;
    #pragma unroll
    for (int mt = 0; mt < 4; mt++)
        #pragma unroll
        for (int nt = 0; nt < 4; nt++) {
            float* d = acc[mt][nt];
            if (do_relu) {
                d[0] = fmaxf(d[0], 0.f); d[1] = fmaxf(d[1], 0.f);
                d[2] = fmaxf(d[2], 0.f); d[3] = fmaxf(d[3], 0.f);
            }
            int r = rbase + mt * 16;
            int c = cbase + nt * 8;
            if (mode == 0) {
                *(float2*)(C + (size_t)r * N + c)       = make_float2(d[0], d[1]);
                *(float2*)(C + (size_t)(r + 8) * N + c) = make_float2(d[2], d[3]);
            } else {
                uint32_t h0, l0, h1, l1;
                split2(d[0], d[1], h0, l0);
                split2(d[2], d[3], h1, l1);
                *(uint32_t*)(Chi + (size_t)r * N + c)       = h0;
                *(uint32_t*)(Clo + (size_t)r * N + c)       = l0;
                *(uint32_t*)(Chi + (size_t)(r + 8) * N + c) = h1;
                *(uint32_t*)(Clo + (size_t)(r + 8) * N + c) = l1;
            }
        }
}

// ---------------- fused fp32 -> split for query/key/value --------------------
__global__ __launch_bounds__(256) void cvt_split3_kernel(
    const float* __restrict__ x0, const float* __restrict__ x1,
    const float* __restrict__ x2,
    __nv_bfloat16* __restrict__ h0p, __nv_bfloat16* __restrict__ l0p,
    __nv_bfloat16* __restrict__ h1p, __nv_bfloat16* __restrict__ l1p,
    __nv_bfloat16* __restrict__ h2p, __nv_bfloat16* __restrict__ l2p,
    int n4)
{
    int i = blockIdx.x * 256 + threadIdx.x;
    if (i >= n4) return;
    const float* x;
    __nv_bfloat16 *hi, *lo;
    if (blockIdx.y == 0)      { x = x0; hi = h0p; lo = l0p; }
    else if (blockIdx.y == 1) { x = x1; hi = h1p; lo = l1p; }
    else                      { x = x2; hi = h2p; lo = l2p; }
    float4 v = ((const float4*)x)[i];
    uint32_t a0, b0, a1, b1;
    split2(v.x, v.y, a0, b0);
    split2(v.z, v.w, a1, b1);
    uint32_t* hp = (uint32_t*)hi;
    uint32_t* lp = (uint32_t*)lo;
    hp[2*i]   = a0;
    hp[2*i+1] = a1;
    lp[2*i]   = b0;
    lp[2*i+1] = b1;
}

// ---------------- fused weight transpose + split (all 6 weights) -------------
// Jobs (32x32 tiles): [0,256) WQ, [256,512) WK, [512,768) WV, [768,1024) WO,
// [1024,2048) W1 (N=2048,K=512), [2048,3072) W2 (N=512,K=2048). grid 3072.
__global__ __launch_bounds__(256) void wtrans_all_kernel(
    const float* __restrict__ WQ, const float* __restrict__ WK,
    const float* __restrict__ WV, const float* __restrict__ WO,
    const float* __restrict__ W1, const float* __restrict__ W2,
    __nv_bfloat16* __restrict__ wqh, __nv_bfloat16* __restrict__ wql,
    __nv_bfloat16* __restrict__ wkh, __nv_bfloat16* __restrict__ wkl,
    __nv_bfloat16* __restrict__ wvh, __nv_bfloat16* __restrict__ wvl,
    __nv_bfloat16* __restrict__ woh, __nv_bfloat16* __restrict__ wol,
    __nv_bfloat16* __restrict__ w1h, __nv_bfloat16* __restrict__ w1l,
    __nv_bfloat16* __restrict__ w2h, __nv_bfloat16* __restrict__ w2l)
{
    __shared__ float t[32][33];
    const int bid = blockIdx.x;
    const float* W; __nv_bfloat16 *Th, *Tl; int K, N, rem;
    if (bid < 1024) {
        K = DIN; N = DIN;
        int job = bid >> 8; rem = bid & 255;
        if (job == 0)      { W = WQ; Th = wqh; Tl = wql; }
        else if (job == 1) { W = WK; Th = wkh; Tl = wkl; }
        else if (job == 2) { W = WV; Th = wvh; Tl = wvl; }
        else               { W = WO; Th = woh; Tl = wol; }
    } else if (bid < 2048) {
        K = DIN; N = DMID; rem = bid - 1024;
        W = W1; Th = w1h; Tl = w1l;
    } else {
        K = DMID; N = DIN; rem = bid - 2048;
        W = W2; Th = w2h; Tl = w2l;
    }
    const int nbx = N / 32;
    const int n0 = (rem % nbx) * 32;
    const int k0 = (rem / nbx) * 32;

    const int tx = threadIdx.x & 31, ty = threadIdx.x >> 5;   // (32, 8)
    #pragma unroll
    for (int i = 0; i < 4; i++)
        t[ty + 8*i][tx] = W[(size_t)(k0 + ty + 8*i) * N + n0 + tx];
    __syncthreads();
    #pragma unroll
    for (int i = 0; i < 4; i++) {
        float v = t[tx][ty + 8*i];
        __nv_bfloat16 h = __float2bfloat16(v);
        __nv_bfloat16 l = __float2bfloat16(v - __bfloat162float(h));
        size_t o = (size_t)(n0 + ty + 8*i) * K + k0 + tx;
        Th[o] = h;
        Tl[o] = l;
    }
}

// ---------------- V transpose -> bf16 hi/lo [bh][dim][key] -------------------
__global__ __launch_bounds__(256) void vtrans_kernel(
    const float* __restrict__ V, __nv_bfloat16* __restrict__ Vth,
    __nv_bfloat16* __restrict__ Vtl)
{
    __shared__ float t[32][33];
    const int tx = threadIdx.x, ty = threadIdx.y;   // block (32, 8)
    const int l0 = blockIdx.x * 32;
    const int d0 = blockIdx.y * 32;
    const int bh = blockIdx.z;                      // b*NH + h
    const int b  = bh >> 3, h = bh & 7;
    #pragma unroll
    for (int i = 0; i < 4; i++)
        t[ty + 8*i][tx] = V[(size_t)(b * LL + l0 + ty + 8*i) * DIN + h * DH + d0 + tx];
    __syncthreads();
    #pragma unroll
    for (int i = 0; i < 4; i++) {
        float v = t[tx][ty + 8*i];                  // (l = l0+tx, d = d0+ty+8i)
        __nv_bfloat16 hh = __float2bfloat16(v);
        __nv_bfloat16 lo = __float2bfloat16(v - __bfloat162float(hh));
        size_t o = ((size_t)bh * DH + d0 + ty + 8*i) * LL + l0 + tx;
        Vth[o] = hh;
        Vtl[o] = lo;
    }
}

// ---------------- HMMA flash attention (R12-validated, 971us champion) -------
#define SRB  144                      // bf16 tile row stride (bytes)
#define FSTR 68                       // fp32 tile stride (floats)
#define S_QH 0
#define S_QL (S_QH + 64 * SRB)        // 9216
#define S_KH (S_QL + 64 * SRB)        // 18432
#define S_KL (S_KH + 64 * SRB)        // 27648
#define S_V0 (S_KL + 64 * SRB)        // 36864  (buf b: H at S_V0+b*18432, L +9216)
#define S_PH (S_V0 + 4 * 64 * SRB)    // 73728
#define S_PL (S_PH + 64 * SRB)        // 82944
#define S_S  (S_PL + 64 * SRB)        // 92160 (fp32 64x68; also mask prefetch target)
#define S_AR (S_S + 64 * FSTR * 4)    // 109568
#define S_LR (S_AR + 256)             // 109824
#define ATT_SMEM (S_LR + 256)         // 110080  (2 CTAs/SM)
__global__ __launch_bounds__(256) void attn_kernel(
    const __nv_bfloat16* __restrict__ Qh, const __nv_bfloat16* __restrict__ Ql,
    const __nv_bfloat16* __restrict__ Kh, const __nv_bfloat16* __restrict__ Kl,
    const __nv_bfloat16* __restrict__ Vth, const __nv_bfloat16* __restrict__ Vtl,
    const float* __restrict__ mask,
    __nv_bfloat16* __restrict__ Oh, __nv_bfloat16* __restrict__ Ol)
{
    extern __shared__ char smem[];
    const uint32_t sb = smem_u32(smem);
    float* Ss   = (float*)(smem + S_S);
    float* arow = (float*)(smem + S_AR);
    float* lrow = (float*)(smem + S_LR);

    const int qt = blockIdx.x;
    const int h  = blockIdx.y;
    const int b  = blockIdx.z;
    const int bh = b * NH + h;

    const int tid  = threadIdx.x;
    const int wid  = tid >> 5;
    const int lane = tid & 31;
    const int tx   = tid & 15;
    const int ty   = tid >> 4;
    const int r0   = ty * 4;
    const int c0   = tx * 4;

    const size_t krow0base = (size_t)b * LL;
    const size_t vrow0 = (size_t)bh * DH;
    const float* maskb = mask + ((size_t)b * LL + qt * 64) * LL;

    auto load_kv_mask = [&](int kt) {
        const size_t krow0 = krow0base + kt * 64;
        const uint32_t svb = sb + S_V0 + (kt & 1) * 18432;
        #pragma unroll
        for (int i = 0; i < 4; i++) {
            int idx = tid + i * 256;
            int op  = idx >> 9;
            int rem = idx & 511;
            int r   = rem >> 3;
            int seg = rem & 7;
            const __nv_bfloat16* src =
                (op ? Kl : Kh) + (krow0 + r) * DIN + h * DH + seg * 8;
            CP_ASYNC16(sb + (op ? S_KL : S_KH) + r * SRB + seg * 16, src);
        }
        #pragma unroll
        for (int i = 0; i < 4; i++) {
            int idx = tid + i * 256;
            int op  = idx >> 9;                    // 0: Vth, 1: Vtl
            int rem = idx & 511;
            int r   = rem >> 3;                    // dim 0..63
            int seg = rem & 7;
            const __nv_bfloat16* src =
                (op ? Vtl : Vth) + (vrow0 + r) * LL + kt * 64 + seg * 8;
            CP_ASYNC16(svb + op * 9216 + r * SRB + seg * 16, src);
        }
        // mask tile [64][64] fp32 into Ss (FSTR-padded rows)
        #pragma unroll
        for (int i = 0; i < 4; i++) {
            int idx = tid + i * 256;               // 0..1023
            int r   = idx >> 4;
            int s   = idx & 15;
            const float* src = maskb + (size_t)r * LL + kt * 64 + s * 4;
            CP_ASYNC16(sb + S_S + r * (FSTR * 4) + s * 16, src);
        }
        CP_COMMIT();
    };

    // ---- prologue: Q + tile 0 (K, V, mask) in one group ----
    {
        const size_t qrow0 = (size_t)(b * LL + qt * 64);
        #pragma unroll
        for (int i = 0; i < 4; i++) {
            int idx = tid + i * 256;
            int op  = idx >> 9;               // 0: Qh, 1: Ql
            int rem = idx & 511;
            int r   = rem >> 3;
            int seg = rem & 7;
            const __nv_bfloat16* src =
                (op ? Ql : Qh) + (qrow0 + r) * DIN + h * DH + seg * 8;
            CP_ASYNC16(sb + (op ? S_QL : S_QH) + r * SRB + seg * 16, src);
        }
        load_kv_mask(0);        // commits (Q included in same group)
        CP_WAIT0();
    }
    __syncthreads();

    // HMMA lane addressing (R5/R8-validated)
    const int a_m  = (lane & 15);
    const int a_kb = (lane >> 4) * 16;
    const int b_n  = (lane & 7) + ((lane >> 4) << 3);
    const int b_kb = ((lane >> 3) & 1) * 16;
    const int qr = (wid & 3) * 16;     // score persona: warp's 16 query rows
    const int kc = (wid >> 2) * 32;    // score persona: warp's 32 key cols
    const int wm = wid & 3;            // PV persona: 16 query rows
    const int wn = wid >> 2;           // PV persona: 32 output dims
    const int rl0 = wm * 16 + (lane >> 2);

    // ---- hoist Q fragments ----
    uint32_t qfh[4][4], qfl[4][4];
    #pragma unroll
    for (int k4 = 0; k4 < 4; k4++) {
        uint32_t ro = (qr + a_m) * SRB + k4 * 32 + a_kb;
        ldsm_x4(qfh[k4], sb + S_QH + ro);
        ldsm_x4(qfl[k4], sb + S_QL + ro);
    }

    float m_run[4], l_run[4];
    #pragma unroll
    for (int i = 0; i < 4; i++) { m_run[i] = -1.0e30f; l_run[i] = 0.f; }

    float oacc[4][4];
    #pragma unroll
    for (int j = 0; j < 4; j++)
        #pragma unroll
        for (int v = 0; v < 4; v++) oacc[j][v] = 0.f;

    const int nkt = LL / 64;
    for (int kt = 0; kt < nkt; kt++) {
        // ---- HMMA scores: warp computes 16x32 sub-tile; in-place mask fuse ----
        {
            float sc[4][4];
            #pragma unroll
            for (int j = 0; j < 4; j++)
                #pragma unroll
                for (int v = 0; v < 4; v++) sc[j][v] = 0.f;

            #pragma unroll
            for (int k4 = 0; k4 < 4; k4++) {
                uint32_t bhf[2][4], blf[2][4];
                #pragma unroll
                for (int np = 0; np < 2; np++) {
                    uint32_t rk = (kc + np * 16 + b_n) * SRB + k4 * 32 + b_kb;
                    ldsm_x4(bhf[np], sb + S_KH + rk);
                    ldsm_x4(blf[np], sb + S_KL + rk);
                }
                #pragma unroll
                for (int j = 0; j < 4; j++) {
                    mma16816(sc[j], qfh[k4], &bhf[j >> 1][(j & 1) * 2]);
                    mma16816(sc[j], qfh[k4], &blf[j >> 1][(j & 1) * 2]);
                    mma16816(sc[j], qfl[k4], &bhf[j >> 1][(j & 1) * 2]);
                }
            }

            const int sr0 = qr + (lane >> 2);
            #pragma unroll
            for (int j = 0; j < 4; j++) {
                int col = kc + j * 8 + 2 * (lane & 3);
                float2 mk0 = *(const float2*)&Ss[sr0 * FSTR + col];       // mask
                float2 mk1 = *(const float2*)&Ss[(sr0 + 8) * FSTR + col];
                *(float2*)&Ss[sr0 * FSTR + col] =
                    make_float2(fmaf(sc[j][0], 0.125f, mk0.x),
                                fmaf(sc[j][1], 0.125f, mk0.y));
                *(float2*)&Ss[(sr0 + 8) * FSTR + col] =
                    make_float2(fmaf(sc[j][2], 0.125f, mk1.x),
                                fmaf(sc[j][3], 0.125f, mk1.y));
            }
        }
        __syncthreads();

        // ---- fp32 online softmax; emit bf16 P hi/lo + alpha ----
        {
            float s[4][4];
            #pragma unroll
            for (int i = 0; i < 4; i++)
                #pragma unroll
                for (int j = 0; j < 4; j++)
                    s[i][j] = Ss[(r0 + i) * FSTR + c0 + j];

            #pragma unroll
            for (int i = 0; i < 4; i++) {
                float ml = fmaxf(fmaxf(s[i][0], s[i][1]), fmaxf(s[i][2], s[i][3]));
                #pragma unroll
                for (int off = 1; off < 16; off <<= 1)
                    ml = fmaxf(ml, __shfl_xor_sync(0xffffffffu, ml, off));

                float mnew  = fmaxf(m_run[i], ml);
                float alpha = __expf(m_run[i] - mnew);
                m_run[i] = mnew;

                float lsum = 0.f;
                #pragma unroll
                for (int j = 0; j < 4; j++) {
                    float p = __expf(s[i][j] - mnew);
                    s[i][j] = p;
                    lsum += p;
                }
                #pragma unroll
                for (int off = 1; off < 16; off <<= 1)
                    lsum += __shfl_xor_sync(0xffffffffu, lsum, off);
                l_run[i] = l_run[i] * alpha + lsum;

                if (tx == 0) arow[r0 + i] = alpha;

                uint32_t h0, l0p, h1, l1p;
                split2(s[i][0], s[i][1], h0, l0p);
                split2(s[i][2], s[i][3], h1, l1p);
                uint32_t off0 = (r0 + i) * SRB + c0 * 2;
                *(uint32_t*)(smem + S_PH + off0)     = h0;
                *(uint32_t*)(smem + S_PH + off0 + 4) = h1;
                *(uint32_t*)(smem + S_PL + off0)     = l0p;
                *(uint32_t*)(smem + S_PL + off0 + 4) = l1p;
            }
        }
        __syncthreads();
        // K free, Ss free, V[(kt+1)&1] free -> prefetch next tile over PV
        if (kt + 1 < nkt) load_kv_mask(kt + 1);

        // ---- PV HMMA: A=P [64 q][64 k], B=Vt buf kt&1 [64 d][64 k] ----
        {
            const uint32_t svb = sb + S_V0 + (kt & 1) * 18432;
            float a0 = arow[rl0];
            float a1 = arow[rl0 + 8];
            #pragma unroll
            for (int j = 0; j < 4; j++) {
                oacc[j][0] *= a0; oacc[j][1] *= a0;
                oacc[j][2] *= a1; oacc[j][3] *= a1;
            }

            #pragma unroll
            for (int k4 = 0; k4 < 4; k4++) {
                uint32_t aph[4], apl[4];
                uint32_t ro = (wm * 16 + a_m) * SRB + k4 * 32 + a_kb;
                ldsm_x4(aph, sb + S_PH + ro);
                ldsm_x4(apl, sb + S_PL + ro);
                uint32_t bvh[2][4], bvl[2][4];
                #pragma unroll
                for (int np = 0; np < 2; np++) {
                    uint32_t rk = (wn * 32 + np * 16 + b_n) * SRB + k4 * 32 + b_kb;
                    ldsm_x4(bvh[np], svb + rk);
                    ldsm_x4(bvl[np], svb + 9216 + rk);
                }
                #pragma unroll
                for (int j = 0; j < 4; j++) {
                    mma16816(oacc[j], aph, &bvh[j >> 1][(j & 1) * 2]);
                    mma16816(oacc[j], aph, &bvl[j >> 1][(j & 1) * 2]);
                    mma16816(oacc[j], apl, &bvh[j >> 1][(j & 1) * 2]);
                }
            }
        }

        if (kt + 1 < nkt) CP_WAIT0();
        __syncthreads();
    }

    // ---- publish l_run, split-bf16 epilogue ----
    if (tx == 0) {
        #pragma unroll
        for (int i = 0; i < 4; i++) lrow[r0 + i] = l_run[i];
    }
    __syncthreads();

    const float inv0 = 1.f / lrow[rl0];
    const float inv1 = 1.f / lrow[rl0 + 8];
    const size_t o0 = ((size_t)(b * LL + qt * 64 + rl0)) * DIN + h * DH
                    + wn * 32 + 2 * (lane & 3);
    const size_t o1 = o0 + 8 * DIN;
    #pragma unroll
    for (int j = 0; j < 4; j++) {
        uint32_t h0, l0p, h1, l1p;
        split2(oacc[j][0] * inv0, oacc[j][1] * inv0, h0, l0p);
        split2(oacc[j][2] * inv1, oacc[j][3] * inv1, h1, l1p);
        *(uint32_t*)(Oh + o0 + 8 * j) = h0;
        *(uint32_t*)(Ol + o0 + 8 * j) = l0p;
        *(uint32_t*)(Oh + o1 + 8 * j) = h1;
        *(uint32_t*)(Ol + o1 + 8 * j) = l1p;
    }
}

// ---------------- residual + LayerNorm (optional split output) ---------------
__global__ __launch_bounds__(128) void ln_residual_kernel(
    const float* __restrict__ x, const float* __restrict__ y,
    float* __restrict__ o,
    __nv_bfloat16* __restrict__ ohi, __nv_bfloat16* __restrict__ olo,
    int emit_split)
{
    const int row = blockIdx.x;
    const int t   = threadIdx.x;
    const float* xr = x + (size_t)row * DIN;
    const float* yr = y + (size_t)row * DIN;

    float v[4];
    float s = 0.f, s2 = 0.f;
    #pragma unroll
    for (int i = 0; i < 4; i++) {
        float a = xr[t + 128 * i] + yr[t + 128 * i];
        v[i] = a;
        s  += a;
        s2 += a * a;
    }
    #pragma unroll
    for (int off = 16; off; off >>= 1) {
        s  += __shfl_xor_sync(0xffffffffu, s,  off);
        s2 += __shfl_xor_sync(0xffffffffu, s2, off);
    }
    __shared__ float ss[4], ss2[4];
    if ((t & 31) == 0) { ss[t >> 5] = s; ss2[t >> 5] = s2; }
    __syncthreads();
    s  = ss[0]  + ss[1]  + ss[2]  + ss[3];
    s2 = ss2[0] + ss2[1] + ss2[2] + ss2[3];

    const float mean = s * (1.f / DIN);
    const float var  = s2 * (1.f / DIN) - mean * mean;
    const float r    = rsqrtf(var + 1e-5f);

    float* orow = o + (size_t)row * DIN;
    #pragma unroll
    for (int i = 0; i < 4; i++) {
        float val = (v[i] - mean) * r;
        orow[t + 128 * i] = val;
        if (emit_split) {
            __nv_bfloat16 hh = __float2bfloat16(val);
            ohi[(size_t)row * DIN + t + 128 * i] = hh;
            olo[(size_t)row * DIN + t + 128 * i] =
                __float2bfloat16(val - __bfloat162float(hh));
        }
    }
}

// ---------------- launch -----------------------------------------------------
extern "C" void kernel_launch(void* const* d_in, const int* in_sizes, int n_in,
                              void* d_out, int out_size)
{
    const float* query = (const float*)d_in[0];
    const float* key   = (const float*)d_in[1];
    const float* value = (const float*)d_in[2];
    const float* mask  = (const float*)d_in[3];
    const float* WQ    = (const float*)d_in[4];
    const float* WK    = (const float*)d_in[5];
    const float* WV    = (const float*)d_in[6];
    const float* WO    = (const float*)d_in[7];
    const float* W1    = (const float*)d_in[8];
    const float* W2    = (const float*)d_in[9];
    float* out = (float*)d_out;

    float *Vp, *tmp, *xa;
    cudaGetSymbolAddress((void**)&Vp,  g_V);
    cudaGetSymbolAddress((void**)&tmp, g_tmp);
    cudaGetSymbolAddress((void**)&xa,  g_xa);

    __nv_bfloat16 *ahi, *alo, *qh, *ql, *kh, *kl, *vh, *vl, *ath, *atl, *vth, *vtl;
    __nv_bfloat16 *wqh, *wql, *wkh, *wkl, *wvh, *wvl;
    __nv_bfloat16 *woh, *wol, *w1h, *w1l, *w2h, *w2l;
    cudaGetSymbolAddress((void**)&ahi, g_ahi);
    cudaGetSymbolAddress((void**)&alo, g_alo);
    cudaGetSymbolAddress((void**)&qh,  g_qh);
    cudaGetSymbolAddress((void**)&ql,  g_ql);
    cudaGetSymbolAddress((void**)&kh,  g_kh);
    cudaGetSymbolAddress((void**)&kl,  g_kl);
    cudaGetSymbolAddress((void**)&vh,  g_vh);
    cudaGetSymbolAddress((void**)&vl,  g_vl);
    cudaGetSymbolAddress((void**)&ath, g_ath);
    cudaGetSymbolAddress((void**)&atl, g_atl);
    cudaGetSymbolAddress((void**)&vth, g_vth);
    cudaGetSymbolAddress((void**)&vtl, g_vtl);
    cudaGetSymbolAddress((void**)&wqh, g_wqh);
    cudaGetSymbolAddress((void**)&wql, g_wql);
    cudaGetSymbolAddress((void**)&wkh, g_wkh);
    cudaGetSymbolAddress((void**)&wkl, g_wkl);
    cudaGetSymbolAddress((void**)&wvh, g_wvh);
    cudaGetSymbolAddress((void**)&wvl, g_wvl);
    cudaGetSymbolAddress((void**)&woh, g_woh);
    cudaGetSymbolAddress((void**)&wol, g_wol);
    cudaGetSymbolAddress((void**)&w1h, g_w1h);
    cudaGetSymbolAddress((void**)&w1l, g_w1l);
    cudaGetSymbolAddress((void**)&w2h, g_w2h);
    cudaGetSymbolAddress((void**)&w2l, g_w2l);

    const int gemm_smem = 2 * STAGEB;                      // 81920 B
    cudaFuncSetAttribute(hgemm3_kernel,
                         cudaFuncAttributeMaxDynamicSharedMemorySize, gemm_smem);
    cudaFuncSetAttribute(attn_kernel,
                         cudaFuncAttributeMaxDynamicSharedMemorySize, ATT_SMEM);

    const int n4_512  = MROWS * DIN / 4;
    const dim3 ggemm512(DIN / 128, MROWS / 128);
    const dim3 ggemm2048(DMID / 128, MROWS / 128);

    // 0: all weight transposes in one launch
    wtrans_all_kernel<<<3072, 256>>>(WQ, WK, WV, WO, W1, W2,
                                     wqh, wql, wkh, wkl, wvh, wvl,
                                     woh, wol, w1h, w1l, w2h, w2l);
    // 1: fused q/k/v input split
    cvt_split3_kernel<<<dim3(n4_512/256, 3), 256>>>(
        query, key, value, ahi, alo, ath, atl, vh, vl, n4_512);
    // 2: V projection   3: V transpose
    hgemm3_kernel<<<ggemm512, 256, gemm_smem>>>(vh, vl, wvh, wvl,
                                                Vp, nullptr, nullptr, DIN, DIN, 0, 0);
    vtrans_kernel<<<dim3(LL/32, DH/32, BB*NH), dim3(32, 8)>>>(Vp, vth, vtl);
    // 4: Q projection   5: K projection  (ncu capture lands here)
    hgemm3_kernel<<<ggemm512, 256, gemm_smem>>>(ahi, alo, wqh, wql,
                                                nullptr, qh, ql, DIN, DIN, 0, 1);
    hgemm3_kernel<<<ggemm512, 256, gemm_smem>>>(ath, atl, wkh, wkl,
                                                nullptr, kh, kl, DIN, DIN, 0, 1);

    // attention (split output into ath/atl, free after K GEMM)
    attn_kernel<<<dim3(LL/64, NH, BB), 256, ATT_SMEM>>>(
        qh, ql, kh, kl, vth, vtl, mask, ath, atl);

    // WO + residual + LN (xa split emitted into qh/ql, free after attention)
    hgemm3_kernel<<<ggemm512, 256, gemm_smem>>>(ath, atl, woh, wol,
                                                tmp, nullptr, nullptr, DIN, DIN, 0, 0);
    ln_residual_kernel<<<MROWS, 128>>>(query, tmp, xa, qh, ql, 1);

    // FFN + residual + LN
    hgemm3_kernel<<<ggemm2048, 256, gemm_smem>>>(qh, ql, w1h, w1l,
                                                 nullptr, ahi, alo, DIN, DMID, 1, 1);
    hgemm3_kernel<<<ggemm512, 256, gemm_smem>>>(ahi, alo, w2h, w2l,
                                                tmp, nullptr, nullptr, DMID, DIN, 0, 0);
    ln_residual_kernel<<<MROWS, 128>>>(xa, tmp, out, nullptr, nullptr, 0);
}